// round 13
// baseline (speedup 1.0000x reference)
#include <cuda_runtime.h>
#include <math.h>

#define NTOK 8192
#define NSEQ 1024
#define NBAT 8
#define NSPLIT 4

typedef unsigned long long u64;

// ---------------- f32x2 packed helpers (Blackwell) ----------------
__device__ __forceinline__ u64 pack2f(float lo, float hi){
  u64 r; asm("mov.b64 %0, {%1, %2};" : "=l"(r) : "f"(lo), "f"(hi)); return r;
}
__device__ __forceinline__ u64 ffma2(u64 a, u64 b, u64 c){
  u64 d; asm("fma.rn.f32x2 %0, %1, %2, %3;" : "=l"(d) : "l"(a), "l"(b), "l"(c)); return d;
}
__device__ __forceinline__ u64 fmul2(u64 a, u64 b){
  u64 d; asm("mul.rn.f32x2 %0, %1, %2;" : "=l"(d) : "l"(a), "l"(b)); return d;
}
__device__ __forceinline__ u64 fadd2(u64 a, u64 b){
  u64 d; asm("add.rn.f32x2 %0, %1, %2;" : "=l"(d) : "l"(a), "l"(b)); return d;
}
__device__ __forceinline__ float hadd2(u64 v){
  float a,b; asm("mov.b64 {%0, %1}, %2;" : "=f"(a), "=f"(b) : "l"(v)); return a+b;
}
__device__ __forceinline__ u64 lo2(float4 v){ return pack2f(v.x, v.y); }
__device__ __forceinline__ u64 hi2(float4 v){ return pack2f(v.z, v.w); }
// ---------------- cp.async helpers ----------------
__device__ __forceinline__ void cpa16(void* s, const void* g){
  unsigned sa = (unsigned)__cvta_generic_to_shared(s);
  asm volatile("cp.async.cg.shared.global [%0], [%1], 16;" :: "r"(sa), "l"(g));
}
__device__ __forceinline__ void cpa_commit(){ asm volatile("cp.async.commit_group;"); }
__device__ __forceinline__ void cpa_wait0(){ asm volatile("cp.async.wait_group 0;"); }

// ---------------- device scratch ----------------
__device__ float g_mv [NTOK*256];
__device__ float g_s  [NTOK*32];
__device__ float g_Q[(size_t)64*NSEQ*20];
__device__ float g_K[(size_t)64*NSEQ*20];
__device__ float g_V[(size_t)64*NSEQ*36];
__device__ float g_Osp[(size_t)64*NSEQ*NSPLIT*38];   // [bh][n][split][36 acc + m + l]

// ---------------- blade tables ----------------
__constant__ int   c_kdiag[16] = {0,1,1,1,1,2,2,2,2,2,2,3,3,3,3,4};
__constant__ int   c_pair [16] = {-1,0,-1,-1,-1,2,3,4,-1,-1,-1,8,9,10,-1,14};
__constant__ int   c_koff [16] = {0,5,0,0,0,6,6,6,0,0,0,7,7,7,0,8};
__constant__ float c_inner[16] = {1,0,1,1,1,0,0,0,1,1,1,0,0,0,1,0};
__constant__ int   c_iblades[8]= {0,2,3,4,8,9,10,14};

// compile-time blade algebra (geometric product)
__host__ __device__ constexpr int blade_mask(int i){
  return i==0?0: i==1?1: i==2?2: i==3?4: i==4?8: i==5?3: i==6?5: i==7?9:
         i==8?6: i==9?10: i==10?12: i==11?7: i==12?11: i==13?13: i==14?14: 15;
}
__host__ __device__ constexpr int mask_idx(int m){
  return m==0?0: m==1?1: m==2?2: m==3?5: m==4?3: m==5?6: m==6?8: m==7?11:
         m==8?4: m==9?7: m==10?9: m==11?12: m==12?10: m==13?13: m==14?14: 15;
}
__host__ __device__ constexpr int pc4(int v){ return (v&1)+((v>>1)&1)+((v>>2)&1)+((v>>3)&1); }
__host__ __device__ constexpr int gp_par(int ma,int mb){
  return ( ((mb&1)?pc4(ma>>1):0) + (((mb>>1)&1)?pc4(ma>>2):0) + (((mb>>2)&1)?pc4(ma>>3):0) ) & 1;
}
template<int I,int J>
__device__ __forceinline__ void gp_term(float (&acc)[16], const float* x, const float* y){
  constexpr int ma = blade_mask(I);
  constexpr int mb = blade_mask(J);
  if constexpr (!(ma & mb & 1)) {
    constexpr int k  = mask_idx(ma ^ mb);
    constexpr int sg = gp_par(ma, mb);
    float p = x[I]*y[J];
    if constexpr (sg) acc[k] -= p; else acc[k] += p;
  }
}
#define GP_ROW(I) \
  gp_term<I,0>(acc,x,y);  gp_term<I,1>(acc,x,y);  gp_term<I,2>(acc,x,y);  gp_term<I,3>(acc,x,y); \
  gp_term<I,4>(acc,x,y);  gp_term<I,5>(acc,x,y);  gp_term<I,6>(acc,x,y);  gp_term<I,7>(acc,x,y); \
  gp_term<I,8>(acc,x,y);  gp_term<I,9>(acc,x,y);  gp_term<I,10>(acc,x,y); gp_term<I,11>(acc,x,y);\
  gp_term<I,12>(acc,x,y); gp_term<I,13>(acc,x,y); gp_term<I,14>(acc,x,y); gp_term<I,15>(acc,x,y);

__device__ __forceinline__ float gelu_f(float v){
  float v3 = v*v*v;
  return 0.5f*v*(1.f + tanhf(0.7978845608028654f*(v + 0.044715f*v3)));
}

// ---- equi building blocks: TWO tokens per call, float4 (LDS.128) loads ----
__device__ __forceinline__ void load_wmv_row(const float* wmv, int o, int kd, int ko, int pr,
                                             u64* wd2, u64* wp2){
  #pragma unroll
  for(int i=0;i<8;i++)
    wd2[i] = pack2f(wmv[o*144 + (2*i)*9 + kd], wmv[o*144 + (2*i+1)*9 + kd]);
  if (pr >= 0){
    #pragma unroll
    for(int i=0;i<8;i++)
      wp2[i] = pack2f(wmv[o*144 + (2*i)*9 + ko], wmv[o*144 + (2*i+1)*9 + ko]);
  }
}
__device__ __forceinline__ void equi_mv_val2(const float* X0, const float* X1, int a, int pr,
    const u64* wd2, const u64* wp2, const u64* wsm2, float& r0, float& r1){
  const float4* A0 = (const float4*)(X0 + a*20);
  const float4* A1 = (const float4*)(X1 + a*20);
  u64 p0, p1, q0, q1;
  {
    float4 f0 = A0[0], f1 = A0[1], g0 = A1[0], g1 = A1[1];
    p0 = fmul2(wd2[0], lo2(f0)); p1 = fmul2(wd2[1], hi2(f0));
    q0 = fmul2(wd2[0], lo2(g0)); q1 = fmul2(wd2[1], hi2(g0));
    p0 = ffma2(wd2[2], lo2(f1), p0); p1 = ffma2(wd2[3], hi2(f1), p1);
    q0 = ffma2(wd2[2], lo2(g1), q0); q1 = ffma2(wd2[3], hi2(g1), q1);
    float4 f2 = A0[2], f3 = A0[3], g2 = A1[2], g3 = A1[3];
    p0 = ffma2(wd2[4], lo2(f2), p0); p1 = ffma2(wd2[5], hi2(f2), p1);
    q0 = ffma2(wd2[4], lo2(g2), q0); q1 = ffma2(wd2[5], hi2(g2), q1);
    p0 = ffma2(wd2[6], lo2(f3), p0); p1 = ffma2(wd2[7], hi2(f3), p1);
    q0 = ffma2(wd2[6], lo2(g3), q0); q1 = ffma2(wd2[7], hi2(g3), q1);
  }
  if (pr >= 0){
    const float4* B0 = (const float4*)(X0 + pr*20);
    const float4* B1 = (const float4*)(X1 + pr*20);
    float4 f0 = B0[0], f1 = B0[1], g0 = B1[0], g1 = B1[1];
    p0 = ffma2(wp2[0], lo2(f0), p0); p1 = ffma2(wp2[1], hi2(f0), p1);
    q0 = ffma2(wp2[0], lo2(g0), q0); q1 = ffma2(wp2[1], hi2(g0), q1);
    p0 = ffma2(wp2[2], lo2(f1), p0); p1 = ffma2(wp2[3], hi2(f1), p1);
    q0 = ffma2(wp2[2], lo2(g1), q0); q1 = ffma2(wp2[3], hi2(g1), q1);
    float4 f2 = B0[2], f3 = B0[3], g2 = B1[2], g3 = B1[3];
    p0 = ffma2(wp2[4], lo2(f2), p0); p1 = ffma2(wp2[5], hi2(f2), p1);
    q0 = ffma2(wp2[4], lo2(g2), q0); q1 = ffma2(wp2[5], hi2(g2), q1);
    p0 = ffma2(wp2[6], lo2(f3), p0); p1 = ffma2(wp2[7], hi2(f3), p1);
    q0 = ffma2(wp2[6], lo2(g3), q0); q1 = ffma2(wp2[7], hi2(g3), q1);
  }
  if (a == 0){
    const float4* S0 = (const float4*)(X0 + 320);
    const float4* S1 = (const float4*)(X1 + 320);
    #pragma unroll
    for(int c=0;c<8;c++){
      float4 f = S0[c], g = S1[c];
      p0 = ffma2(wsm2[2*c], lo2(f), p0); p1 = ffma2(wsm2[2*c+1], hi2(f), p1);
      q0 = ffma2(wsm2[2*c], lo2(g), q0); q1 = ffma2(wsm2[2*c+1], hi2(g), q1);
    }
  }
  r0 = hadd2(fadd2(p0, p1));
  r1 = hadd2(fadd2(q0, q1));
}
__device__ __forceinline__ void equi_s_val2(const float* X0, const float* X1,
    const u64* wss2, const u64* wms2, float& r0, float& r1){
  const float4* S0 = (const float4*)(X0 + 320);
  const float4* S1 = (const float4*)(X1 + 320);
  u64 p0, p1, q0, q1;
  {
    float4 f = S0[0], g = S1[0];
    p0 = fmul2(wss2[0], lo2(f)); p1 = fmul2(wss2[1], hi2(f));
    q0 = fmul2(wss2[0], lo2(g)); q1 = fmul2(wss2[1], hi2(g));
  }
  #pragma unroll
  for(int c=1;c<8;c++){
    float4 f = S0[c], g = S1[c];
    p0 = ffma2(wss2[2*c], lo2(f), p0); p1 = ffma2(wss2[2*c+1], hi2(f), p1);
    q0 = ffma2(wss2[2*c], lo2(g), q0); q1 = ffma2(wss2[2*c+1], hi2(g), q1);
  }
  const float4* Z0 = (const float4*)(X0);
  const float4* Z1 = (const float4*)(X1);
  #pragma unroll
  for(int c=0;c<4;c++){
    float4 f = Z0[c], g = Z1[c];
    p0 = ffma2(wms2[2*c], lo2(f), p0); p1 = ffma2(wms2[2*c+1], hi2(f), p1);
    q0 = ffma2(wms2[2*c], lo2(g), q0); q1 = ffma2(wms2[2*c+1], hi2(g), q1);
  }
  r0 = hadd2(fadd2(p0, p1));
  r1 = hadd2(fadd2(q0, q1));
}

// ---------------- embed ----------------
__global__ void embed_kernel(const float* __restrict__ inp,
                             const float* __restrict__ win_mv,
                             const float* __restrict__ win_bs){
  int idx = blockIdx.x*blockDim.x + threadIdx.x;
  if (idx < NTOK*16){
    int t = idx>>4, o = idx&15;
    float x = inp[t*3+0], y = inp[t*3+1], z = inp[t*3+2];
    float w3 = win_mv[o*9+3], w8 = win_mv[o*9+8];
    float* M = g_mv + (size_t)t*256 + o*16;
    #pragma unroll
    for(int a=0;a<16;a++) M[a]=0.f;
    M[11] = -z*w3;  M[12] = y*w3;  M[13] = -x*w3;  M[14] = w3;  M[15] = w8;
  } else if (idx < NTOK*16 + NTOK*32){
    int r = idx - NTOK*16; int t = r>>5, j = r&31;
    g_s[t*32+j] = win_bs[j];
  }
}

// ---------------- LN + QKV equi, staged coalesced pack (layer 0 only) ------
__global__ void __launch_bounds__(864) qkv_kernel(
    const float* __restrict__ wmv, const float* __restrict__ wsm,
    const float* __restrict__ wms, const float* __restrict__ wss)
{
  constexpr int T = 16, NT = 864;
  extern __shared__ float sm[];
  float* SX = sm;            // T*352
  float* SY = sm + T*352;    // T*864
  const int tid = threadIdx.x;
  const size_t t0 = (size_t)blockIdx.x * T;
  const int b = (int)(t0 >> 10), n0 = (int)(t0 & 1023);

  for(int idx=tid; idx<T*256; idx+=NT){
    int t = idx>>8, r = idx&255, i = r>>4, a = r&15;
    SX[t*352 + a*20 + i] = g_mv[(t0+t)*256 + r];
  }
  for(int idx=tid; idx<T*32; idx+=NT){
    int t = idx>>5, j = idx&31;
    SX[t*352 + 320 + j] = g_s[(t0+t)*32 + j];
  }
  __syncthreads();

  { // LN: warp w -> token w
    int w = tid>>5, lane = tid&31;
    if (w < T){
      float* X = SX + w*352;
      int a = lane>>1;
      int base = a*20 + (lane&1)*8;
      float msk = c_inner[a];
      float ss = 0.f;
      #pragma unroll
      for(int r=0;r<8;r++){ float v = X[base+r]; ss += v*v*msk; }
      #pragma unroll
      for(int off=16;off;off>>=1) ss += __shfl_xor_sync(0xffffffffu, ss, off);
      float sc = rsqrtf(ss*0.0625f + 1e-6f);
      #pragma unroll
      for(int r=0;r<8;r++) X[base+r] *= sc;
      float v = X[320+lane];
      float s2 = v*v;
      #pragma unroll
      for(int off=16;off;off>>=1) s2 += __shfl_xor_sync(0xffffffffu, s2, off);
      X[320+lane] = v * rsqrtf(s2*0.03125f + 1e-6f);
    }
  }
  __syncthreads();

  if (tid < 768){
    int o = tid % 48, a = tid / 48;
    int kd = c_kdiag[a], pr = c_pair[a], ko = c_koff[a];
    u64 wd2[8], wp2[8], wsm2[16];
    load_wmv_row(wmv, o, kd, ko, pr, wd2, wp2);
    if (a == 0){
      #pragma unroll
      for(int j=0;j<16;j++) wsm2[j] = pack2f(wsm[o*32+2*j], wsm[o*32+2*j+1]);
    }
    for(int t=0; t<T; t+=2){
      float r0, r1;
      equi_mv_val2(SX + t*352, SX + (t+1)*352, a, pr, wd2, wp2, wsm2, r0, r1);
      SY[t*864 + a*48 + o] = r0;
      SY[(t+1)*864 + a*48 + o] = r1;
    }
  } else {
    int o = tid - 768;  // 0..95
    u64 wss2[16], wms2[8];
    #pragma unroll
    for(int j=0;j<16;j++) wss2[j] = pack2f(wss[o*32+2*j], wss[o*32+2*j+1]);
    #pragma unroll
    for(int i=0;i<8;i++)  wms2[i] = pack2f(wms[o*16+2*i], wms[o*16+2*i+1]);
    for(int t=0; t<T; t+=2){
      float r0, r1;
      equi_s_val2(SX + t*352, SX + (t+1)*352, wss2, wms2, r0, r1);
      SY[t*864 + 768 + o] = r0;
      SY[(t+1)*864 + 768 + o] = r1;
    }
  }
  __syncthreads();

  for(int idx=tid; idx<8*T*20; idx+=NT){           // Q
    int h = idx/(T*20), rem = idx%(T*20), t = rem/20, e = rem%20;
    float v;
    if (e < 16){ int ci=e>>3, ib=e&7, a=c_iblades[ib]; v = SY[t*864 + a*48 + (h*2+ci)]; }
    else       { v = SY[t*864 + 768 + h*4 + (e-16)]; }
    g_Q[((size_t)(b*8+h)*NSEQ + n0 + t)*20 + e] = v;
  }
  for(int idx=tid; idx<8*T*20; idx+=NT){           // K
    int h = idx/(T*20), rem = idx%(T*20), t = rem/20, e = rem%20;
    float v;
    if (e < 16){ int ci=e>>3, ib=e&7, a=c_iblades[ib]; v = SY[t*864 + a*48 + (16 + h*2+ci)]; }
    else       { v = SY[t*864 + 768 + 32 + h*4 + (e-16)]; }
    g_K[((size_t)(b*8+h)*NSEQ + n0 + t)*20 + e] = v;
  }
  for(int idx=tid; idx<8*T*36; idx+=NT){           // V
    int h = idx/(T*36), rem = idx%(T*36), t = rem/36, e = rem%36;
    float v;
    if (e < 32){ int ci=e>>4, a=e&15; v = SY[t*864 + a*48 + (32 + h*2+ci)]; }
    else       { v = SY[t*864 + 768 + 64 + h*4 + (e-32)]; }
    g_V[((size_t)(b*8+h)*NSEQ + n0 + t)*36 + e] = v;
  }
}

// ---------------- attention (split-KV x4, 1 query/thread, 64-key tiles) ----
__global__ void __launch_bounds__(128) attn_kernel(){
  const int bh = blockIdx.x, qt = blockIdx.y, z = blockIdx.z, tid = threadIdx.x;
  const int qi = qt*128 + tid;
  const float SCALE = 0.22360679774997896f;  // 1/sqrt(20)

  extern __shared__ float4 dyn4[];
  float4* sk4 = dyn4;            // 2 x 320
  float4* sv4 = dyn4 + 640;      // 2 x 576

  u64 q[10];
  {
    const float* qp = g_Q + ((size_t)bh*NSEQ + qi)*20;
    #pragma unroll
    for(int c=0;c<10;c++) q[c] = pack2f(qp[2*c]*SCALE, qp[2*c+1]*SCALE);
  }
  float m0 = -1e30f, l0 = 0.f;
  u64 acc[18];
  #pragma unroll
  for(int c=0;c<18;c++) acc[c] = 0ull;

  const float4* kp = (const float4*)(g_K + (size_t)bh*NSEQ*20) + z*256*5;
  const float4* vp = (const float4*)(g_V + (size_t)bh*NSEQ*36) + z*256*9;

  // preload tile 0 (64 keys): K 320 f4 + V 576 f4 over 128 threads
  for(int idx=tid; idx<320; idx+=128) cpa16(&sk4[idx], &kp[idx]);
  for(int idx=tid; idx<576; idx+=128) cpa16(&sv4[idx], &vp[idx]);
  cpa_commit();
  cpa_wait0();
  __syncthreads();

  for(int kt=0; kt<4; kt++){
    const int cur = kt & 1, nxt = cur ^ 1;
    if (kt < 3){
      const float4* kpn = kp + (kt+1)*320;
      const float4* vpn = vp + (kt+1)*576;
      for(int idx=tid; idx<320; idx+=128) cpa16(&sk4[nxt*320 + idx], &kpn[idx]);
      for(int idx=tid; idx<576; idx+=128) cpa16(&sv4[nxt*576 + idx], &vpn[idx]);
      cpa_commit();
    }
    const float4* skc = sk4 + cur*320;
    const float4* svc = sv4 + cur*576;

    #pragma unroll 2
    for(int j=0; j<64; j++){
      const float4* kk4 = skc + j*5;
      float4 k0 = kk4[0], k1 = kk4[1], k2 = kk4[2], k3 = kk4[3], k4 = kk4[4];
      // 4 short chains for lower dot latency
      u64 ta = fmul2(q[0], lo2(k0));
      u64 tb = fmul2(q[1], hi2(k0));
      u64 tc = fmul2(q[2], lo2(k1));
      u64 td = fmul2(q[3], hi2(k1));
      ta = ffma2(q[4], lo2(k2), ta);
      tb = ffma2(q[5], hi2(k2), tb);
      tc = ffma2(q[6], lo2(k3), tc);
      td = ffma2(q[7], hi2(k3), td);
      ta = ffma2(q[8], lo2(k4), ta);
      tb = ffma2(q[9], hi2(k4), tb);
      float s0 = hadd2(fadd2(fadd2(ta, tb), fadd2(tc, td)));
      float p0;
      if (s0 > m0){
        float cc = __expf(m0 - s0); m0 = s0; l0 = l0*cc + 1.f;
        u64 cp = pack2f(cc, cc);
        #pragma unroll
        for(int c=0;c<18;c++) acc[c] = fmul2(acc[c], cp);
        p0 = 1.f;
      } else { p0 = __expf(s0 - m0); l0 += p0; }
      u64 pp = pack2f(p0, p0);
      const float4* vv4 = svc + j*9;
      #pragma unroll
      for(int i=0;i<9;i++){
        float4 v4 = vv4[i];
        acc[2*i]   = ffma2(pp, lo2(v4), acc[2*i]);
        acc[2*i+1] = ffma2(pp, hi2(v4), acc[2*i+1]);
      }
    }
    if (kt < 3){
      cpa_wait0();
      __syncthreads();
    }
  }
  float* op = g_Osp + ((size_t)(bh*NSEQ + qi)*NSPLIT + z)*38;
  #pragma unroll
  for(int c=0;c<18;c++) ((u64*)op)[c] = acc[c];
  op[36] = m0; op[37] = l0;
}

// ---- fused: merge + out-proj + res + LN + mlp1 + GP + mlp2 + res (+ next QKV)
template<bool FQ>
__global__ void __launch_bounds__(576) block2_kernel(
    const float* __restrict__ ao_wmv, const float* __restrict__ ao_wsm,
    const float* __restrict__ ao_wms, const float* __restrict__ ao_wss,
    const float* __restrict__ m1_wmv, const float* __restrict__ m1_wsm,
    const float* __restrict__ m1_wms, const float* __restrict__ m1_wss,
    const float* __restrict__ m2_wmv, const float* __restrict__ m2_wsm,
    const float* __restrict__ m2_wms, const float* __restrict__ m2_wss,
    const float* __restrict__ nq_wmv, const float* __restrict__ nq_wsm,
    const float* __restrict__ nq_wms, const float* __restrict__ nq_wss)
{
  constexpr int T = 16, NT = 576, SRS = 304;
  extern __shared__ float sm[];
  float* SA  = sm;                 // T*352  attn-out (blade-major); later SX2
  float* SR  = SA + T*352;         // T*304  residual [o*17+a], scalars at 272
  float* SW  = SR + T*SRS;         // T*8*NSPLIT merge weights
  float* SH  = SW + T*8*NSPLIT;    // T*864 region: mlp1 hidden (608) / qkv SY (864)
  float* SX2 = SA;
  const int tid = threadIdx.x;
  const size_t t0 = (size_t)blockIdx.x * T;
  const int b = (int)(t0 >> 10), n0 = (int)(t0 & 1023);

  // ---- stage 0: merge weights + residual loads ----
  if (tid < T*8){
    int t = tid>>3, h = tid&7;
    const float* p = g_Osp + (((size_t)(b*8+h)*NSEQ + n0 + t)*NSPLIT)*38;
    float m[NSPLIT], l[NSPLIT];
    float mm = -1e30f;
    #pragma unroll
    for(int z=0;z<NSPLIT;z++){ m[z]=p[z*38+36]; l[z]=p[z*38+37]; mm = fmaxf(mm, m[z]); }
    float den = 0.f, w[NSPLIT];
    #pragma unroll
    for(int z=0;z<NSPLIT;z++){ w[z] = __expf(m[z]-mm); den += l[z]*w[z]; }
    float inv = 1.f/den;
    #pragma unroll
    for(int z=0;z<NSPLIT;z++) SW[tid*NSPLIT + z] = w[z]*inv;
  }
  for(int idx=tid; idx<T*256; idx+=NT){
    int t = idx>>8, r = idx&255;
    SR[t*SRS + (r>>4)*17 + (r&15)] = g_mv[(t0+t)*256 + r];
  }
  for(int idx=tid; idx<T*32; idx+=NT){
    int t = idx>>5, j = idx&31;
    SR[t*SRS + 272 + j] = g_s[(t0+t)*32 + j];
  }
  __syncthreads();

  // ---- stage 1: merged attn-out -> SA (blade-major) ----
  for(int idx=tid; idx<T*288; idx+=NT){
    int t = idx/288, r = idx%288;
    int h = r/36, e = r%36;
    const float* p = g_Osp + (((size_t)(b*8+h)*NSEQ + n0 + t)*NSPLIT)*38;
    const float* wv = SW + (t*8+h)*NSPLIT;
    float v = 0.f;
    #pragma unroll
    for(int z=0;z<NSPLIT;z++) v += p[z*38 + e] * wv[z];
    if (e < 32){ int ci=e>>4, a=e&15; SA[t*352 + a*20 + (h*2+ci)] = v; }
    else       { SA[t*352 + 320 + h*4 + (e-32)] = v; }
  }
  __syncthreads();

  // ---- stage 2: out-projection equi + residual add into SR ----
  {
    int out = tid % 288, tp = tid / 288;   // tp in {0,1}
    if (out < 256){
      int o = out & 15, a = out >> 4;
      int kd = c_kdiag[a], pr = c_pair[a], ko = c_koff[a];
      u64 wd2[8], wp2[8], wsm2[16];
      load_wmv_row(ao_wmv, o, kd, ko, pr, wd2, wp2);
      if (a == 0){
        #pragma unroll
        for(int j=0;j<16;j++) wsm2[j] = pack2f(ao_wsm[o*32+2*j], ao_wsm[o*32+2*j+1]);
      }
      #pragma unroll
      for(int tt=0; tt<4; tt++){
        int t = tp + tt*4;
        float r0, r1;
        equi_mv_val2(SA + t*352, SA + (t+2)*352, a, pr, wd2, wp2, wsm2, r0, r1);
        SR[t*SRS + o*17 + a] += r0;
        SR[(t+2)*SRS + o*17 + a] += r1;
      }
    } else {
      int o = out - 256;
      u64 wss2[16], wms2[8];
      #pragma unroll
      for(int j=0;j<16;j++) wss2[j] = pack2f(ao_wss[o*32+2*j], ao_wss[o*32+2*j+1]);
      #pragma unroll
      for(int i=0;i<8;i++)  wms2[i] = pack2f(ao_wms[o*16+2*i], ao_wms[o*16+2*i+1]);
      #pragma unroll
      for(int tt=0; tt<4; tt++){
        int t = tp + tt*4;
        float r0, r1;
        equi_s_val2(SA + t*352, SA + (t+2)*352, wss2, wms2, r0, r1);
        SR[t*SRS + 272 + o] += r0;
        SR[(t+2)*SRS + 272 + o] += r1;
      }
    }
  }
  __syncthreads();

  // ---- stage 3: LN(SR) -> SX2 ----
  {
    int w = tid>>5, lane = tid&31;
    if (w < T){
      const float* R = SR + w*SRS;
      float ss = 0.f;
      #pragma unroll
      for(int r=0;r<8;r++){
        int li = lane + 32*r; int o = li>>4, a = li&15;
        float v = R[o*17 + a]; ss += v*v*c_inner[a];
      }
      #pragma unroll
      for(int off=16;off;off>>=1) ss += __shfl_xor_sync(0xffffffffu, ss, off);
      float sc = rsqrtf(ss*0.0625f + 1e-6f);
      #pragma unroll
      for(int r=0;r<8;r++){
        int li = lane + 32*r; int o = li>>4, a = li&15;
        SX2[w*352 + a*20 + o] = R[o*17 + a]*sc;
      }
      float v = R[272+lane];
      float s2 = v*v;
      #pragma unroll
      for(int off=16;off;off>>=1) s2 += __shfl_xor_sync(0xffffffffu, s2, off);
      SX2[w*352 + 320 + lane] = v * rsqrtf(s2*0.03125f + 1e-6f);
    }
  }
  __syncthreads();

  // ---- stage 4: mlp1 equi (512 mv outs + 64 s outs) -> SH (stride 608) ----
  if (tid < 512){
    int o = tid % 32, a = tid / 32;
    int kd = c_kdiag[a], pr = c_pair[a], ko = c_koff[a];
    u64 wd2[8], wp2[8], wsm2[16];
    load_wmv_row(m1_wmv, o, kd, ko, pr, wd2, wp2);
    if (a == 0){
      #pragma unroll
      for(int j=0;j<16;j++) wsm2[j] = pack2f(m1_wsm[o*32+2*j], m1_wsm[o*32+2*j+1]);
    }
    for(int t=0; t<T; t+=2){
      float r0, r1;
      equi_mv_val2(SX2 + t*352, SX2 + (t+1)*352, a, pr, wd2, wp2, wsm2, r0, r1);
      SH[t*608 + o*17 + a] = r0;
      SH[(t+1)*608 + o*17 + a] = r1;
    }
  } else {
    int o = tid - 512;  // 0..63
    u64 wss2[16], wms2[8];
    #pragma unroll
    for(int j=0;j<16;j++) wss2[j] = pack2f(m1_wss[o*32+2*j], m1_wss[o*32+2*j+1]);
    #pragma unroll
    for(int i=0;i<8;i++)  wms2[i] = pack2f(m1_wms[o*16+2*i], m1_wms[o*16+2*i+1]);
    for(int t=0; t<T; t+=2){
      float r0, r1;
      equi_s_val2(SX2 + t*352, SX2 + (t+1)*352, wss2, wms2, r0, r1);
      SH[t*608 + 544 + o] = r0;
      SH[(t+1)*608 + 544 + o] = r1;
    }
  }
  __syncthreads();

  // ---- stage 5: geometric product + gated gelu -> SX2 ----
  for(int idx=tid; idx<T*48; idx+=NT){
    if (idx < T*16){
      int t = idx>>4, c = idx&15;
      const float* h1 = SH + t*608 + c*17;
      const float* h2 = SH + t*608 + (16+c)*17;
      float x[16], y[16], acc[16];
      #pragma unroll
      for(int i=0;i<16;i++){ x[i]=h1[i]; y[i]=h2[i]; acc[i]=0.f; }
      GP_ROW(0)  GP_ROW(1)  GP_ROW(2)  GP_ROW(3)
      GP_ROW(4)  GP_ROW(5)  GP_ROW(6)  GP_ROW(7)
      GP_ROW(8)  GP_ROW(9)  GP_ROW(10) GP_ROW(11)
      GP_ROW(12) GP_ROW(13) GP_ROW(14) GP_ROW(15)
      float g = gelu_f(acc[0]);
      #pragma unroll
      for(int a=0;a<16;a++) SX2[t*352 + a*20 + c] = acc[a]*g;
    } else {
      int r = idx - T*16; int t = r>>5, j = r&31;
      const float* hs = SH + t*608 + 544;
      SX2[t*352 + 320 + j] = hs[j] * gelu_f(hs[32+j]);
    }
  }
  __syncthreads();

  // ---- stage 6: mlp2 equi + residual add into SR ----
  {
    int out = tid % 288, tp = tid / 288;
    if (out < 256){
      int o = out & 15, a = out >> 4;
      int kd = c_kdiag[a], pr = c_pair[a], ko = c_koff[a];
      u64 wd2[8], wp2[8], wsm2[16];
      load_wmv_row(m2_wmv, o, kd, ko, pr, wd2, wp2);
      if (a == 0){
        #pragma unroll
        for(int j=0;j<16;j++) wsm2[j] = pack2f(m2_wsm[o*32+2*j], m2_wsm[o*32+2*j+1]);
      }
      #pragma unroll
      for(int tt=0; tt<4; tt++){
        int t = tp + tt*4;
        float r0, r1;
        equi_mv_val2(SX2 + t*352, SX2 + (t+2)*352, a, pr, wd2, wp2, wsm2, r0, r1);
        SR[t*SRS + o*17 + a] += r0;
        SR[(t+2)*SRS + o*17 + a] += r1;
      }
    } else {
      int o = out - 256;
      u64 wss2[16], wms2[8];
      #pragma unroll
      for(int j=0;j<16;j++) wss2[j] = pack2f(m2_wss[o*32+2*j], m2_wss[o*32+2*j+1]);
      #pragma unroll
      for(int i=0;i<8;i++)  wms2[i] = pack2f(m2_wms[o*16+2*i], m2_wms[o*16+2*i+1]);
      #pragma unroll
      for(int tt=0; tt<4; tt++){
        int t = tp + tt*4;
        float r0, r1;
        equi_s_val2(SX2 + t*352, SX2 + (t+2)*352, wss2, wms2, r0, r1);
        SR[t*SRS + 272 + o] += r0;
        SR[(t+2)*SRS + 272 + o] += r1;
      }
    }
  }
  __syncthreads();

  // ---- stage 7: store residual to global ----
  for(int idx=tid; idx<T*256; idx+=NT){
    int t = idx>>8, r = idx&255;
    g_mv[(t0+t)*256 + r] = SR[t*SRS + (r>>4)*17 + (r&15)];
  }
  for(int idx=tid; idx<T*32; idx+=NT){
    int t = idx>>5, j = idx&31;
    g_s[(t0+t)*32 + j] = SR[t*SRS + 272 + j];
  }

  if (!FQ) return;

  // ---- stage 8: LN(SR) -> SX2 (for next layer's QKV) ----
  {
    int w = tid>>5, lane = tid&31;
    if (w < T){
      const float* R = SR + w*SRS;
      float ss = 0.f;
      #pragma unroll
      for(int r=0;r<8;r++){
        int li = lane + 32*r; int o = li>>4, a = li&15;
        float v = R[o*17 + a]; ss += v*v*c_inner[a];
      }
      #pragma unroll
      for(int off=16;off;off>>=1) ss += __shfl_xor_sync(0xffffffffu, ss, off);
      float sc = rsqrtf(ss*0.0625f + 1e-6f);
      #pragma unroll
      for(int r=0;r<8;r++){
        int li = lane + 32*r; int o = li>>4, a = li&15;
        SX2[w*352 + a*20 + o] = R[o*17 + a]*sc;
      }
      float v = R[272+lane];
      float s2 = v*v;
      #pragma unroll
      for(int off=16;off;off>>=1) s2 += __shfl_xor_sync(0xffffffffu, s2, off);
      SX2[w*352 + 320 + lane] = v * rsqrtf(s2*0.03125f + 1e-6f);
    }
  }
  __syncthreads();

  // ---- stage 9: next-layer QKV equi -> SH as SY (stride 864) ----
  for(int out = tid; out < 864; out += NT){
    if (out < 768){
      int o = out % 48, a = out / 48;
      int kd = c_kdiag[a], pr = c_pair[a], ko = c_koff[a];
      u64 wd2[8], wp2[8], wsm2[16];
      load_wmv_row(nq_wmv, o, kd, ko, pr, wd2, wp2);
      if (a == 0){
        #pragma unroll
        for(int j=0;j<16;j++) wsm2[j] = pack2f(nq_wsm[o*32+2*j], nq_wsm[o*32+2*j+1]);
      }
      for(int t=0; t<T; t+=2){
        float r0, r1;
        equi_mv_val2(SX2 + t*352, SX2 + (t+1)*352, a, pr, wd2, wp2, wsm2, r0, r1);
        SH[t*864 + a*48 + o] = r0;
        SH[(t+1)*864 + a*48 + o] = r1;
      }
    } else {
      int o = out - 768;  // 0..95
      u64 wss2[16], wms2[8];
      #pragma unroll
      for(int j=0;j<16;j++) wss2[j] = pack2f(nq_wss[o*32+2*j], nq_wss[o*32+2*j+1]);
      #pragma unroll
      for(int i=0;i<8;i++)  wms2[i] = pack2f(nq_wms[o*16+2*i], nq_wms[o*16+2*i+1]);
      for(int t=0; t<T; t+=2){
        float r0, r1;
        equi_s_val2(SX2 + t*352, SX2 + (t+1)*352, wss2, wms2, r0, r1);
        SH[t*864 + 768 + o] = r0;
        SH[(t+1)*864 + 768 + o] = r1;
      }
    }
  }
  __syncthreads();

  // ---- stage 10: pack Q/K/V ----
  for(int idx=tid; idx<8*T*20; idx+=NT){           // Q
    int h = idx/(T*20), rem = idx%(T*20), t = rem/20, e = rem%20;
    float v;
    if (e < 16){ int ci=e>>3, ib=e&7, a=c_iblades[ib]; v = SH[t*864 + a*48 + (h*2+ci)]; }
    else       { v = SH[t*864 + 768 + h*4 + (e-16)]; }
    g_Q[((size_t)(b*8+h)*NSEQ + n0 + t)*20 + e] = v;
  }
  for(int idx=tid; idx<8*T*20; idx+=NT){           // K
    int h = idx/(T*20), rem = idx%(T*20), t = rem/20, e = rem%20;
    float v;
    if (e < 16){ int ci=e>>3, ib=e&7, a=c_iblades[ib]; v = SH[t*864 + a*48 + (16 + h*2+ci)]; }
    else       { v = SH[t*864 + 768 + 32 + h*4 + (e-16)]; }
    g_K[((size_t)(b*8+h)*NSEQ + n0 + t)*20 + e] = v;
  }
  for(int idx=tid; idx<8*T*36; idx+=NT){           // V
    int h = idx/(T*36), rem = idx%(T*36), t = rem/36, e = rem%36;
    float v;
    if (e < 32){ int ci=e>>4, a=e&15; v = SH[t*864 + a*48 + (32 + h*2+ci)]; }
    else       { v = SH[t*864 + 768 + 64 + h*4 + (e-32)]; }
    g_V[((size_t)(b*8+h)*NSEQ + n0 + t)*36 + e] = v;
  }
}

// ---------------- final projection + mean ----------------
__global__ void final_kernel(const float* __restrict__ wout_mv,
                             const float* __restrict__ wout_sm,
                             float* __restrict__ out){
  int b = blockIdx.x, tid = threadIdx.x;
  __shared__ float red[256];
  float acc = 0.f;
  for(int n=tid; n<NSEQ; n+=256){
    size_t t = (size_t)b*NSEQ + n;
    const float* M = g_mv + t*256;
    const float* S = g_s + t*32;
    float v = 0.f;
    #pragma unroll
    for(int i=0;i<16;i++) v += wout_mv[i*9] * M[i*16];
    #pragma unroll
    for(int j=0;j<32;j++) v += wout_sm[j] * S[j];
    acc += v;
  }
  red[tid] = acc; __syncthreads();
  for(int s=128; s; s>>=1){ if (tid < s) red[tid] += red[tid+s]; __syncthreads(); }
  if (tid == 0) out[b] = red[0] * (1.f/NSEQ);
}

// ---------------- host ----------------
extern "C" void kernel_launch(void* const* d_in, const int* in_sizes, int n_in,
                              void* d_out, int out_size) {
  const float* inputs    = (const float*)d_in[0];
  const float* win_mv    = (const float*)d_in[1];
  const float* win_bs    = (const float*)d_in[3];
  const float* qkv_wmv   = (const float*)d_in[4];
  const float* qkv_wsm   = (const float*)d_in[5];
  const float* qkv_wms   = (const float*)d_in[6];
  const float* qkv_wss   = (const float*)d_in[7];
  const float* aout_wmv  = (const float*)d_in[8];
  const float* aout_wsm  = (const float*)d_in[9];
  const float* aout_wms  = (const float*)d_in[10];
  const float* aout_wss  = (const float*)d_in[11];
  const float* m1_wmv    = (const float*)d_in[12];
  const float* m1_wsm    = (const float*)d_in[13];
  const float* m1_wms    = (const float*)d_in[14];
  const float* m1_wss    = (const float*)d_in[15];
  const float* m2_wmv    = (const float*)d_in[16];
  const float* m2_wsm    = (const float*)d_in[17];
  const float* m2_wms    = (const float*)d_in[18];
  const float* m2_wss    = (const float*)d_in[19];
  const float* wout_mv   = (const float*)d_in[20];
  const float* wout_sm   = (const float*)d_in[21];

  const int smem_qkv  = (16*352 + 16*864) * 4;                        // 77824
  const int smem_blk  = (16*352 + 16*304 + 16*8*NSPLIT + 16*864) * 4; // 99328
  const int smem_attn = (2*320 + 2*576) * 16;                         // 28672
  cudaFuncSetAttribute((const void*)qkv_kernel,
                       cudaFuncAttributeMaxDynamicSharedMemorySize, smem_qkv);
  cudaFuncSetAttribute((const void*)block2_kernel<true>,
                       cudaFuncAttributeMaxDynamicSharedMemorySize, smem_blk);
  cudaFuncSetAttribute((const void*)block2_kernel<false>,
                       cudaFuncAttributeMaxDynamicSharedMemorySize, smem_blk);
  cudaFuncSetAttribute((const void*)attn_kernel,
                       cudaFuncAttributeMaxDynamicSharedMemorySize, smem_attn);

  embed_kernel<<<(NTOK*48 + 255)/256, 256>>>(inputs, win_mv, win_bs);

  qkv_kernel<<<NTOK/16, 864, smem_qkv>>>(
      qkv_wmv, qkv_wsm, qkv_wms, qkv_wss);

  for (int l = 0; l < 8; l++){
    attn_kernel<<<dim3(64, NSEQ/128, NSPLIT), 128, smem_attn>>>();
    if (l < 7){
      int ln = l + 1;
      block2_kernel<true><<<NTOK/16, 576, smem_blk>>>(
          aout_wmv + (size_t)l*16*16*9, aout_wsm + (size_t)l*16*32,
          aout_wms + (size_t)l*32*16,   aout_wss + (size_t)l*32*32,
          m1_wmv  + (size_t)l*32*16*9,  m1_wsm  + (size_t)l*32*32,
          m1_wms  + (size_t)l*64*16,    m1_wss  + (size_t)l*64*32,
          m2_wmv  + (size_t)l*16*16*9,  m2_wsm  + (size_t)l*16*32,
          m2_wms  + (size_t)l*32*16,    m2_wss  + (size_t)l*32*32,
          qkv_wmv + (size_t)ln*48*16*9, qkv_wsm + (size_t)ln*48*32,
          qkv_wms + (size_t)ln*96*16,   qkv_wss + (size_t)ln*96*32);
    } else {
      block2_kernel<false><<<NTOK/16, 576, smem_blk>>>(
          aout_wmv + (size_t)l*16*16*9, aout_wsm + (size_t)l*16*32,
          aout_wms + (size_t)l*32*16,   aout_wss + (size_t)l*32*32,
          m1_wmv  + (size_t)l*32*16*9,  m1_wsm  + (size_t)l*32*32,
          m1_wms  + (size_t)l*64*16,    m1_wss  + (size_t)l*64*32,
          m2_wmv  + (size_t)l*16*16*9,  m2_wsm  + (size_t)l*16*32,
          m2_wms  + (size_t)l*32*16,    m2_wss  + (size_t)l*32*32,
          qkv_wmv, qkv_wsm, qkv_wms, qkv_wss);
    }
  }

  final_kernel<<<NBAT, 256>>>(wout_mv, wout_sm, (float*)d_out);
}

// round 14
// speedup vs baseline: 1.0755x; 1.0755x over previous
#include <cuda_runtime.h>
#include <math.h>

#define NTOK 8192
#define NSEQ 1024
#define NBAT 8
#define NSPLIT 4

typedef unsigned long long u64;

// ---------------- f32x2 packed helpers (Blackwell) ----------------
__device__ __forceinline__ u64 pack2f(float lo, float hi){
  u64 r; asm("mov.b64 %0, {%1, %2};" : "=l"(r) : "f"(lo), "f"(hi)); return r;
}
__device__ __forceinline__ u64 ffma2(u64 a, u64 b, u64 c){
  u64 d; asm("fma.rn.f32x2 %0, %1, %2, %3;" : "=l"(d) : "l"(a), "l"(b), "l"(c)); return d;
}
__device__ __forceinline__ u64 fmul2(u64 a, u64 b){
  u64 d; asm("mul.rn.f32x2 %0, %1, %2;" : "=l"(d) : "l"(a), "l"(b)); return d;
}
__device__ __forceinline__ u64 fadd2(u64 a, u64 b){
  u64 d; asm("add.rn.f32x2 %0, %1, %2;" : "=l"(d) : "l"(a), "l"(b)); return d;
}
__device__ __forceinline__ float hadd2(u64 v){
  float a,b; asm("mov.b64 {%0, %1}, %2;" : "=f"(a), "=f"(b) : "l"(v)); return a+b;
}
__device__ __forceinline__ u64 lo2(float4 v){ return pack2f(v.x, v.y); }
__device__ __forceinline__ u64 hi2(float4 v){ return pack2f(v.z, v.w); }
// ---------------- cp.async helpers ----------------
__device__ __forceinline__ void cpa16(void* s, const void* g){
  unsigned sa = (unsigned)__cvta_generic_to_shared(s);
  asm volatile("cp.async.cg.shared.global [%0], [%1], 16;" :: "r"(sa), "l"(g));
}
__device__ __forceinline__ void cpa_commit(){ asm volatile("cp.async.commit_group;"); }
__device__ __forceinline__ void cpa_wait0(){ asm volatile("cp.async.wait_group 0;"); }

// ---------------- device scratch ----------------
__device__ float g_mv [NTOK*256];
__device__ float g_s  [NTOK*32];
__device__ float g_Q[(size_t)64*NSEQ*20];
__device__ float g_K[(size_t)64*NSEQ*20];
__device__ float g_V[(size_t)64*NSEQ*36];
__device__ float g_Osp[(size_t)64*NSEQ*NSPLIT*38];   // [bh][n][split][36 acc + m + l]

// ---------------- blade tables ----------------
__constant__ int   c_kdiag[16] = {0,1,1,1,1,2,2,2,2,2,2,3,3,3,3,4};
__constant__ int   c_pair [16] = {-1,0,-1,-1,-1,2,3,4,-1,-1,-1,8,9,10,-1,14};
__constant__ int   c_koff [16] = {0,5,0,0,0,6,6,6,0,0,0,7,7,7,0,8};
__constant__ float c_inner[16] = {1,0,1,1,1,0,0,0,1,1,1,0,0,0,1,0};
__constant__ int   c_iblades[8]= {0,2,3,4,8,9,10,14};

// compile-time blade algebra (geometric product)
__host__ __device__ constexpr int blade_mask(int i){
  return i==0?0: i==1?1: i==2?2: i==3?4: i==4?8: i==5?3: i==6?5: i==7?9:
         i==8?6: i==9?10: i==10?12: i==11?7: i==12?11: i==13?13: i==14?14: 15;
}
__host__ __device__ constexpr int mask_idx(int m){
  return m==0?0: m==1?1: m==2?2: m==3?5: m==4?3: m==5?6: m==6?8: m==7?11:
         m==8?4: m==9?7: m==10?9: m==11?12: m==12?10: m==13?13: m==14?14: 15;
}
__host__ __device__ constexpr int pc4(int v){ return (v&1)+((v>>1)&1)+((v>>2)&1)+((v>>3)&1); }
__host__ __device__ constexpr int gp_par(int ma,int mb){
  return ( ((mb&1)?pc4(ma>>1):0) + (((mb>>1)&1)?pc4(ma>>2):0) + (((mb>>2)&1)?pc4(ma>>3):0) ) & 1;
}
template<int I,int J>
__device__ __forceinline__ void gp_term(float (&acc)[16], const float* x, const float* y){
  constexpr int ma = blade_mask(I);
  constexpr int mb = blade_mask(J);
  if constexpr (!(ma & mb & 1)) {
    constexpr int k  = mask_idx(ma ^ mb);
    constexpr int sg = gp_par(ma, mb);
    float p = x[I]*y[J];
    if constexpr (sg) acc[k] -= p; else acc[k] += p;
  }
}
#define GP_ROW(I) \
  gp_term<I,0>(acc,x,y);  gp_term<I,1>(acc,x,y);  gp_term<I,2>(acc,x,y);  gp_term<I,3>(acc,x,y); \
  gp_term<I,4>(acc,x,y);  gp_term<I,5>(acc,x,y);  gp_term<I,6>(acc,x,y);  gp_term<I,7>(acc,x,y); \
  gp_term<I,8>(acc,x,y);  gp_term<I,9>(acc,x,y);  gp_term<I,10>(acc,x,y); gp_term<I,11>(acc,x,y);\
  gp_term<I,12>(acc,x,y); gp_term<I,13>(acc,x,y); gp_term<I,14>(acc,x,y); gp_term<I,15>(acc,x,y);

__device__ __forceinline__ float gelu_f(float v){
  float v3 = v*v*v;
  return 0.5f*v*(1.f + tanhf(0.7978845608028654f*(v + 0.044715f*v3)));
}

// ---- equi building blocks: TWO tokens per call, float4 (LDS.128) loads ----
__device__ __forceinline__ void load_wmv_row(const float* wmv, int o, int kd, int ko, int pr,
                                             u64* wd2, u64* wp2){
  #pragma unroll
  for(int i=0;i<8;i++)
    wd2[i] = pack2f(wmv[o*144 + (2*i)*9 + kd], wmv[o*144 + (2*i+1)*9 + kd]);
  if (pr >= 0){
    #pragma unroll
    for(int i=0;i<8;i++)
      wp2[i] = pack2f(wmv[o*144 + (2*i)*9 + ko], wmv[o*144 + (2*i+1)*9 + ko]);
  }
}
__device__ __forceinline__ void equi_mv_val2(const float* X0, const float* X1, int a, int pr,
    const u64* wd2, const u64* wp2, const u64* wsm2, float& r0, float& r1){
  const float4* A0 = (const float4*)(X0 + a*20);
  const float4* A1 = (const float4*)(X1 + a*20);
  u64 p0, p1, q0, q1;
  {
    float4 f0 = A0[0], f1 = A0[1], g0 = A1[0], g1 = A1[1];
    p0 = fmul2(wd2[0], lo2(f0)); p1 = fmul2(wd2[1], hi2(f0));
    q0 = fmul2(wd2[0], lo2(g0)); q1 = fmul2(wd2[1], hi2(g0));
    p0 = ffma2(wd2[2], lo2(f1), p0); p1 = ffma2(wd2[3], hi2(f1), p1);
    q0 = ffma2(wd2[2], lo2(g1), q0); q1 = ffma2(wd2[3], hi2(g1), q1);
    float4 f2 = A0[2], f3 = A0[3], g2 = A1[2], g3 = A1[3];
    p0 = ffma2(wd2[4], lo2(f2), p0); p1 = ffma2(wd2[5], hi2(f2), p1);
    q0 = ffma2(wd2[4], lo2(g2), q0); q1 = ffma2(wd2[5], hi2(g2), q1);
    p0 = ffma2(wd2[6], lo2(f3), p0); p1 = ffma2(wd2[7], hi2(f3), p1);
    q0 = ffma2(wd2[6], lo2(g3), q0); q1 = ffma2(wd2[7], hi2(g3), q1);
  }
  if (pr >= 0){
    const float4* B0 = (const float4*)(X0 + pr*20);
    const float4* B1 = (const float4*)(X1 + pr*20);
    float4 f0 = B0[0], f1 = B0[1], g0 = B1[0], g1 = B1[1];
    p0 = ffma2(wp2[0], lo2(f0), p0); p1 = ffma2(wp2[1], hi2(f0), p1);
    q0 = ffma2(wp2[0], lo2(g0), q0); q1 = ffma2(wp2[1], hi2(g0), q1);
    p0 = ffma2(wp2[2], lo2(f1), p0); p1 = ffma2(wp2[3], hi2(f1), p1);
    q0 = ffma2(wp2[2], lo2(g1), q0); q1 = ffma2(wp2[3], hi2(g1), q1);
    float4 f2 = B0[2], f3 = B0[3], g2 = B1[2], g3 = B1[3];
    p0 = ffma2(wp2[4], lo2(f2), p0); p1 = ffma2(wp2[5], hi2(f2), p1);
    q0 = ffma2(wp2[4], lo2(g2), q0); q1 = ffma2(wp2[5], hi2(g2), q1);
    p0 = ffma2(wp2[6], lo2(f3), p0); p1 = ffma2(wp2[7], hi2(f3), p1);
    q0 = ffma2(wp2[6], lo2(g3), q0); q1 = ffma2(wp2[7], hi2(g3), q1);
  }
  if (a == 0){
    const float4* S0 = (const float4*)(X0 + 320);
    const float4* S1 = (const float4*)(X1 + 320);
    #pragma unroll
    for(int c=0;c<8;c++){
      float4 f = S0[c], g = S1[c];
      p0 = ffma2(wsm2[2*c], lo2(f), p0); p1 = ffma2(wsm2[2*c+1], hi2(f), p1);
      q0 = ffma2(wsm2[2*c], lo2(g), q0); q1 = ffma2(wsm2[2*c+1], hi2(g), q1);
    }
  }
  r0 = hadd2(fadd2(p0, p1));
  r1 = hadd2(fadd2(q0, q1));
}
__device__ __forceinline__ void equi_s_val2(const float* X0, const float* X1,
    const u64* wss2, const u64* wms2, float& r0, float& r1){
  const float4* S0 = (const float4*)(X0 + 320);
  const float4* S1 = (const float4*)(X1 + 320);
  u64 p0, p1, q0, q1;
  {
    float4 f = S0[0], g = S1[0];
    p0 = fmul2(wss2[0], lo2(f)); p1 = fmul2(wss2[1], hi2(f));
    q0 = fmul2(wss2[0], lo2(g)); q1 = fmul2(wss2[1], hi2(g));
  }
  #pragma unroll
  for(int c=1;c<8;c++){
    float4 f = S0[c], g = S1[c];
    p0 = ffma2(wss2[2*c], lo2(f), p0); p1 = ffma2(wss2[2*c+1], hi2(f), p1);
    q0 = ffma2(wss2[2*c], lo2(g), q0); q1 = ffma2(wss2[2*c+1], hi2(g), q1);
  }
  const float4* Z0 = (const float4*)(X0);
  const float4* Z1 = (const float4*)(X1);
  #pragma unroll
  for(int c=0;c<4;c++){
    float4 f = Z0[c], g = Z1[c];
    p0 = ffma2(wms2[2*c], lo2(f), p0); p1 = ffma2(wms2[2*c+1], hi2(f), p1);
    q0 = ffma2(wms2[2*c], lo2(g), q0); q1 = ffma2(wms2[2*c+1], hi2(g), q1);
  }
  r0 = hadd2(fadd2(p0, p1));
  r1 = hadd2(fadd2(q0, q1));
}

// ---------------- embed ----------------
__global__ void embed_kernel(const float* __restrict__ inp,
                             const float* __restrict__ win_mv,
                             const float* __restrict__ win_bs){
  int idx = blockIdx.x*blockDim.x + threadIdx.x;
  if (idx < NTOK*16){
    int t = idx>>4, o = idx&15;
    float x = inp[t*3+0], y = inp[t*3+1], z = inp[t*3+2];
    float w3 = win_mv[o*9+3], w8 = win_mv[o*9+8];
    float* M = g_mv + (size_t)t*256 + o*16;
    #pragma unroll
    for(int a=0;a<16;a++) M[a]=0.f;
    M[11] = -z*w3;  M[12] = y*w3;  M[13] = -x*w3;  M[14] = w3;  M[15] = w8;
  } else if (idx < NTOK*16 + NTOK*32){
    int r = idx - NTOK*16; int t = r>>5, j = r&31;
    g_s[t*32+j] = win_bs[j];
  }
}

// ---------------- LN + QKV equi, staged coalesced pack (layer 0 only) ------
__global__ void __launch_bounds__(864) qkv_kernel(
    const float* __restrict__ wmv, const float* __restrict__ wsm,
    const float* __restrict__ wms, const float* __restrict__ wss)
{
  constexpr int T = 16, NT = 864;
  extern __shared__ float sm[];
  float* SX = sm;            // T*352
  float* SY = sm + T*352;    // T*864
  const int tid = threadIdx.x;
  const size_t t0 = (size_t)blockIdx.x * T;
  const int b = (int)(t0 >> 10), n0 = (int)(t0 & 1023);

  for(int idx=tid; idx<T*256; idx+=NT){
    int t = idx>>8, r = idx&255, i = r>>4, a = r&15;
    SX[t*352 + a*20 + i] = g_mv[(t0+t)*256 + r];
  }
  for(int idx=tid; idx<T*32; idx+=NT){
    int t = idx>>5, j = idx&31;
    SX[t*352 + 320 + j] = g_s[(t0+t)*32 + j];
  }
  __syncthreads();

  { // LN: warp w -> token w
    int w = tid>>5, lane = tid&31;
    if (w < T){
      float* X = SX + w*352;
      int a = lane>>1;
      int base = a*20 + (lane&1)*8;
      float msk = c_inner[a];
      float ss = 0.f;
      #pragma unroll
      for(int r=0;r<8;r++){ float v = X[base+r]; ss += v*v*msk; }
      #pragma unroll
      for(int off=16;off;off>>=1) ss += __shfl_xor_sync(0xffffffffu, ss, off);
      float sc = rsqrtf(ss*0.0625f + 1e-6f);
      #pragma unroll
      for(int r=0;r<8;r++) X[base+r] *= sc;
      float v = X[320+lane];
      float s2 = v*v;
      #pragma unroll
      for(int off=16;off;off>>=1) s2 += __shfl_xor_sync(0xffffffffu, s2, off);
      X[320+lane] = v * rsqrtf(s2*0.03125f + 1e-6f);
    }
  }
  __syncthreads();

  if (tid < 768){
    int o = tid % 48, a = tid / 48;
    int kd = c_kdiag[a], pr = c_pair[a], ko = c_koff[a];
    u64 wd2[8], wp2[8], wsm2[16];
    load_wmv_row(wmv, o, kd, ko, pr, wd2, wp2);
    if (a == 0){
      #pragma unroll
      for(int j=0;j<16;j++) wsm2[j] = pack2f(wsm[o*32+2*j], wsm[o*32+2*j+1]);
    }
    for(int t=0; t<T; t+=2){
      float r0, r1;
      equi_mv_val2(SX + t*352, SX + (t+1)*352, a, pr, wd2, wp2, wsm2, r0, r1);
      SY[t*864 + a*48 + o] = r0;
      SY[(t+1)*864 + a*48 + o] = r1;
    }
  } else {
    int o = tid - 768;  // 0..95
    u64 wss2[16], wms2[8];
    #pragma unroll
    for(int j=0;j<16;j++) wss2[j] = pack2f(wss[o*32+2*j], wss[o*32+2*j+1]);
    #pragma unroll
    for(int i=0;i<8;i++)  wms2[i] = pack2f(wms[o*16+2*i], wms[o*16+2*i+1]);
    for(int t=0; t<T; t+=2){
      float r0, r1;
      equi_s_val2(SX + t*352, SX + (t+1)*352, wss2, wms2, r0, r1);
      SY[t*864 + 768 + o] = r0;
      SY[(t+1)*864 + 768 + o] = r1;
    }
  }
  __syncthreads();

  for(int idx=tid; idx<8*T*20; idx+=NT){           // Q
    int h = idx/(T*20), rem = idx%(T*20), t = rem/20, e = rem%20;
    float v;
    if (e < 16){ int ci=e>>3, ib=e&7, a=c_iblades[ib]; v = SY[t*864 + a*48 + (h*2+ci)]; }
    else       { v = SY[t*864 + 768 + h*4 + (e-16)]; }
    g_Q[((size_t)(b*8+h)*NSEQ + n0 + t)*20 + e] = v;
  }
  for(int idx=tid; idx<8*T*20; idx+=NT){           // K
    int h = idx/(T*20), rem = idx%(T*20), t = rem/20, e = rem%20;
    float v;
    if (e < 16){ int ci=e>>3, ib=e&7, a=c_iblades[ib]; v = SY[t*864 + a*48 + (16 + h*2+ci)]; }
    else       { v = SY[t*864 + 768 + 32 + h*4 + (e-16)]; }
    g_K[((size_t)(b*8+h)*NSEQ + n0 + t)*20 + e] = v;
  }
  for(int idx=tid; idx<8*T*36; idx+=NT){           // V
    int h = idx/(T*36), rem = idx%(T*36), t = rem/36, e = rem%36;
    float v;
    if (e < 32){ int ci=e>>4, a=e&15; v = SY[t*864 + a*48 + (32 + h*2+ci)]; }
    else       { v = SY[t*864 + 768 + 64 + h*4 + (e-32)]; }
    g_V[((size_t)(b*8+h)*NSEQ + n0 + t)*36 + e] = v;
  }
}

// ---------------- attention (split-KV x4, 2 q/thread, 128-key tiles) -------
__global__ void __launch_bounds__(128) attn_kernel(){
  const int bh = blockIdx.x, qt = blockIdx.y, z = blockIdx.z, tid = threadIdx.x;
  const int qi0 = qt*256 + tid;
  const float SCALE = 0.22360679774997896f;  // 1/sqrt(20)

  extern __shared__ float4 dyn4[];
  float4* sk4 = dyn4;            // 2 x 640
  float4* sv4 = dyn4 + 1280;     // 2 x 1152

  u64 q0[10], q1[10];
  {
    const float* qp0 = g_Q + ((size_t)bh*NSEQ + qi0)*20;
    const float* qp1 = qp0 + 128*20;
    #pragma unroll
    for(int c=0;c<10;c++){
      q0[c] = pack2f(qp0[2*c]*SCALE, qp0[2*c+1]*SCALE);
      q1[c] = pack2f(qp1[2*c]*SCALE, qp1[2*c+1]*SCALE);
    }
  }
  float m0=-1e30f, l0=0.f, m1=-1e30f, l1=0.f;
  u64 a0[18], a1[18];
  #pragma unroll
  for(int c=0;c<18;c++){ a0[c]=0ull; a1[c]=0ull; }

  const int kt0 = z*2;
  const float4* kp = (const float4*)(g_K + (size_t)bh*NSEQ*20) + kt0*128*5;
  const float4* vp = (const float4*)(g_V + (size_t)bh*NSEQ*36) + kt0*128*9;

  #pragma unroll
  for(int i=0;i<5;i++) cpa16(&sk4[tid + 128*i], &kp[tid + 128*i]);
  #pragma unroll
  for(int i=0;i<9;i++) cpa16(&sv4[tid + 128*i], &vp[tid + 128*i]);
  cpa_commit();
  cpa_wait0();
  __syncthreads();

  for(int ki=0; ki<2; ki++){
    const int cur = ki & 1, nxt = cur ^ 1;
    if (ki < 1){
      const float4* kpn = kp + 128*5;
      const float4* vpn = vp + 128*9;
      #pragma unroll
      for(int i=0;i<5;i++) cpa16(&sk4[nxt*640 + tid + 128*i], &kpn[tid + 128*i]);
      #pragma unroll
      for(int i=0;i<9;i++) cpa16(&sv4[nxt*1152 + tid + 128*i], &vpn[tid + 128*i]);
      cpa_commit();
    }
    const float4* skc = sk4 + cur*640;
    const float4* svc = sv4 + cur*1152;

    #pragma unroll 2
    for(int j=0; j<128; j++){
      const float4* kk4 = skc + j*5;
      float4 k0 = kk4[0], k1 = kk4[1], k2 = kk4[2], k3 = kk4[3], k4 = kk4[4];
      u64 t0a = fmul2(q0[0], lo2(k0)), t0b = fmul2(q0[1], hi2(k0));
      u64 t1a = fmul2(q1[0], lo2(k0)), t1b = fmul2(q1[1], hi2(k0));
      t0a = ffma2(q0[2], lo2(k1), t0a); t0b = ffma2(q0[3], hi2(k1), t0b);
      t1a = ffma2(q1[2], lo2(k1), t1a); t1b = ffma2(q1[3], hi2(k1), t1b);
      t0a = ffma2(q0[4], lo2(k2), t0a); t0b = ffma2(q0[5], hi2(k2), t0b);
      t1a = ffma2(q1[4], lo2(k2), t1a); t1b = ffma2(q1[5], hi2(k2), t1b);
      t0a = ffma2(q0[6], lo2(k3), t0a); t0b = ffma2(q0[7], hi2(k3), t0b);
      t1a = ffma2(q1[6], lo2(k3), t1a); t1b = ffma2(q1[7], hi2(k3), t1b);
      t0a = ffma2(q0[8], lo2(k4), t0a); t0b = ffma2(q0[9], hi2(k4), t0b);
      t1a = ffma2(q1[8], lo2(k4), t1a); t1b = ffma2(q1[9], hi2(k4), t1b);
      float s0 = hadd2(fadd2(t0a, t0b));
      float s1 = hadd2(fadd2(t1a, t1b));
      float p0, p1;
      if (s0 > m0){
        float cc = __expf(m0 - s0); m0 = s0; l0 = l0*cc + 1.f;
        u64 cp = pack2f(cc, cc);
        #pragma unroll
        for(int c=0;c<18;c++) a0[c] = fmul2(a0[c], cp);
        p0 = 1.f;
      } else { p0 = __expf(s0 - m0); l0 += p0; }
      if (s1 > m1){
        float cc = __expf(m1 - s1); m1 = s1; l1 = l1*cc + 1.f;
        u64 cp = pack2f(cc, cc);
        #pragma unroll
        for(int c=0;c<18;c++) a1[c] = fmul2(a1[c], cp);
        p1 = 1.f;
      } else { p1 = __expf(s1 - m1); l1 += p1; }
      u64 pp0 = pack2f(p0, p0), pp1 = pack2f(p1, p1);
      const float4* vv4 = svc + j*9;
      #pragma unroll
      for(int i=0;i<9;i++){
        float4 v4 = vv4[i];
        u64 vl = lo2(v4), vh = hi2(v4);
        a0[2*i]   = ffma2(pp0, vl, a0[2*i]);
        a0[2*i+1] = ffma2(pp0, vh, a0[2*i+1]);
        a1[2*i]   = ffma2(pp1, vl, a1[2*i]);
        a1[2*i+1] = ffma2(pp1, vh, a1[2*i+1]);
      }
    }
    if (ki < 1){
      cpa_wait0();
      __syncthreads();
    }
  }
  float* op0 = g_Osp + ((size_t)(bh*NSEQ + qi0)*NSPLIT + z)*38;
  float* op1 = g_Osp + ((size_t)(bh*NSEQ + qi0 + 128)*NSPLIT + z)*38;
  #pragma unroll
  for(int c=0;c<18;c++){
    ((u64*)op0)[c] = a0[c];
    ((u64*)op1)[c] = a1[c];
  }
  op0[36] = m0; op0[37] = l0;
  op1[36] = m1; op1[37] = l1;
}

// ---- fused: merge + out-proj + res + LN + mlp1 + GP + mlp2 + res (+ next QKV)
template<bool FQ>
__global__ void __launch_bounds__(576) block2_kernel(
    const float* __restrict__ ao_wmv, const float* __restrict__ ao_wsm,
    const float* __restrict__ ao_wms, const float* __restrict__ ao_wss,
    const float* __restrict__ m1_wmv, const float* __restrict__ m1_wsm,
    const float* __restrict__ m1_wms, const float* __restrict__ m1_wss,
    const float* __restrict__ m2_wmv, const float* __restrict__ m2_wsm,
    const float* __restrict__ m2_wms, const float* __restrict__ m2_wss,
    const float* __restrict__ nq_wmv, const float* __restrict__ nq_wsm,
    const float* __restrict__ nq_wms, const float* __restrict__ nq_wss)
{
  constexpr int T = 16, NT = 576, SRS = 304;
  extern __shared__ float sm[];
  float* SA  = sm;                 // T*352  attn-out (blade-major); later SX2
  float* SR  = SA + T*352;         // T*304  residual [o*17+a], scalars at 272
  float* SW  = SR + T*SRS;         // T*8*NSPLIT merge weights
  float* SH  = SW + T*8*NSPLIT;    // T*864 region: mlp1 hidden (608) / qkv SY (864)
  float* SX2 = SA;
  const int tid = threadIdx.x;
  const size_t t0 = (size_t)blockIdx.x * T;
  const int b = (int)(t0 >> 10), n0 = (int)(t0 & 1023);

  // ---- stage 0: merge weights + residual loads ----
  if (tid < T*8){
    int t = tid>>3, h = tid&7;
    const float* p = g_Osp + (((size_t)(b*8+h)*NSEQ + n0 + t)*NSPLIT)*38;
    float m[NSPLIT], l[NSPLIT];
    float mm = -1e30f;
    #pragma unroll
    for(int z=0;z<NSPLIT;z++){ m[z]=p[z*38+36]; l[z]=p[z*38+37]; mm = fmaxf(mm, m[z]); }
    float den = 0.f, w[NSPLIT];
    #pragma unroll
    for(int z=0;z<NSPLIT;z++){ w[z] = __expf(m[z]-mm); den += l[z]*w[z]; }
    float inv = 1.f/den;
    #pragma unroll
    for(int z=0;z<NSPLIT;z++) SW[tid*NSPLIT + z] = w[z]*inv;
  }
  for(int idx=tid; idx<T*256; idx+=NT){
    int t = idx>>8, r = idx&255;
    SR[t*SRS + (r>>4)*17 + (r&15)] = g_mv[(t0+t)*256 + r];
  }
  for(int idx=tid; idx<T*32; idx+=NT){
    int t = idx>>5, j = idx&31;
    SR[t*SRS + 272 + j] = g_s[(t0+t)*32 + j];
  }
  __syncthreads();

  // ---- stage 1: merged attn-out -> SA (blade-major) ----
  for(int idx=tid; idx<T*288; idx+=NT){
    int t = idx/288, r = idx%288;
    int h = r/36, e = r%36;
    const float* p = g_Osp + (((size_t)(b*8+h)*NSEQ + n0 + t)*NSPLIT)*38;
    const float* wv = SW + (t*8+h)*NSPLIT;
    float v = 0.f;
    #pragma unroll
    for(int z=0;z<NSPLIT;z++) v += p[z*38 + e] * wv[z];
    if (e < 32){ int ci=e>>4, a=e&15; SA[t*352 + a*20 + (h*2+ci)] = v; }
    else       { SA[t*352 + 320 + h*4 + (e-32)] = v; }
  }
  __syncthreads();

  // ---- stage 2: out-projection equi + residual add into SR ----
  {
    int out = tid % 288, tp = tid / 288;   // tp in {0,1}
    if (out < 256){
      int o = out & 15, a = out >> 4;
      int kd = c_kdiag[a], pr = c_pair[a], ko = c_koff[a];
      u64 wd2[8], wp2[8], wsm2[16];
      load_wmv_row(ao_wmv, o, kd, ko, pr, wd2, wp2);
      if (a == 0){
        #pragma unroll
        for(int j=0;j<16;j++) wsm2[j] = pack2f(ao_wsm[o*32+2*j], ao_wsm[o*32+2*j+1]);
      }
      #pragma unroll
      for(int tt=0; tt<4; tt++){
        int t = tp + tt*4;
        float r0, r1;
        equi_mv_val2(SA + t*352, SA + (t+2)*352, a, pr, wd2, wp2, wsm2, r0, r1);
        SR[t*SRS + o*17 + a] += r0;
        SR[(t+2)*SRS + o*17 + a] += r1;
      }
    } else {
      int o = out - 256;
      u64 wss2[16], wms2[8];
      #pragma unroll
      for(int j=0;j<16;j++) wss2[j] = pack2f(ao_wss[o*32+2*j], ao_wss[o*32+2*j+1]);
      #pragma unroll
      for(int i=0;i<8;i++)  wms2[i] = pack2f(ao_wms[o*16+2*i], ao_wms[o*16+2*i+1]);
      #pragma unroll
      for(int tt=0; tt<4; tt++){
        int t = tp + tt*4;
        float r0, r1;
        equi_s_val2(SA + t*352, SA + (t+2)*352, wss2, wms2, r0, r1);
        SR[t*SRS + 272 + o] += r0;
        SR[(t+2)*SRS + 272 + o] += r1;
      }
    }
  }
  __syncthreads();

  // ---- stage 3: LN(SR) -> SX2 ----
  {
    int w = tid>>5, lane = tid&31;
    if (w < T){
      const float* R = SR + w*SRS;
      float ss = 0.f;
      #pragma unroll
      for(int r=0;r<8;r++){
        int li = lane + 32*r; int o = li>>4, a = li&15;
        float v = R[o*17 + a]; ss += v*v*c_inner[a];
      }
      #pragma unroll
      for(int off=16;off;off>>=1) ss += __shfl_xor_sync(0xffffffffu, ss, off);
      float sc = rsqrtf(ss*0.0625f + 1e-6f);
      #pragma unroll
      for(int r=0;r<8;r++){
        int li = lane + 32*r; int o = li>>4, a = li&15;
        SX2[w*352 + a*20 + o] = R[o*17 + a]*sc;
      }
      float v = R[272+lane];
      float s2 = v*v;
      #pragma unroll
      for(int off=16;off;off>>=1) s2 += __shfl_xor_sync(0xffffffffu, s2, off);
      SX2[w*352 + 320 + lane] = v * rsqrtf(s2*0.03125f + 1e-6f);
    }
  }
  __syncthreads();

  // ---- stage 4: mlp1 equi (512 mv outs + 64 s outs) -> SH (stride 608) ----
  if (tid < 512){
    int o = tid % 32, a = tid / 32;
    int kd = c_kdiag[a], pr = c_pair[a], ko = c_koff[a];
    u64 wd2[8], wp2[8], wsm2[16];
    load_wmv_row(m1_wmv, o, kd, ko, pr, wd2, wp2);
    if (a == 0){
      #pragma unroll
      for(int j=0;j<16;j++) wsm2[j] = pack2f(m1_wsm[o*32+2*j], m1_wsm[o*32+2*j+1]);
    }
    for(int t=0; t<T; t+=2){
      float r0, r1;
      equi_mv_val2(SX2 + t*352, SX2 + (t+1)*352, a, pr, wd2, wp2, wsm2, r0, r1);
      SH[t*608 + o*17 + a] = r0;
      SH[(t+1)*608 + o*17 + a] = r1;
    }
  } else {
    int o = tid - 512;  // 0..63
    u64 wss2[16], wms2[8];
    #pragma unroll
    for(int j=0;j<16;j++) wss2[j] = pack2f(m1_wss[o*32+2*j], m1_wss[o*32+2*j+1]);
    #pragma unroll
    for(int i=0;i<8;i++)  wms2[i] = pack2f(m1_wms[o*16+2*i], m1_wms[o*16+2*i+1]);
    for(int t=0; t<T; t+=2){
      float r0, r1;
      equi_s_val2(SX2 + t*352, SX2 + (t+1)*352, wss2, wms2, r0, r1);
      SH[t*608 + 544 + o] = r0;
      SH[(t+1)*608 + 544 + o] = r1;
    }
  }
  __syncthreads();

  // ---- stage 5: geometric product + gated gelu -> SX2 ----
  for(int idx=tid; idx<T*48; idx+=NT){
    if (idx < T*16){
      int t = idx>>4, c = idx&15;
      const float* h1 = SH + t*608 + c*17;
      const float* h2 = SH + t*608 + (16+c)*17;
      float x[16], y[16], acc[16];
      #pragma unroll
      for(int i=0;i<16;i++){ x[i]=h1[i]; y[i]=h2[i]; acc[i]=0.f; }
      GP_ROW(0)  GP_ROW(1)  GP_ROW(2)  GP_ROW(3)
      GP_ROW(4)  GP_ROW(5)  GP_ROW(6)  GP_ROW(7)
      GP_ROW(8)  GP_ROW(9)  GP_ROW(10) GP_ROW(11)
      GP_ROW(12) GP_ROW(13) GP_ROW(14) GP_ROW(15)
      float g = gelu_f(acc[0]);
      #pragma unroll
      for(int a=0;a<16;a++) SX2[t*352 + a*20 + c] = acc[a]*g;
    } else {
      int r = idx - T*16; int t = r>>5, j = r&31;
      const float* hs = SH + t*608 + 544;
      SX2[t*352 + 320 + j] = hs[j] * gelu_f(hs[32+j]);
    }
  }
  __syncthreads();

  // ---- stage 6: mlp2 equi + residual add into SR ----
  {
    int out = tid % 288, tp = tid / 288;
    if (out < 256){
      int o = out & 15, a = out >> 4;
      int kd = c_kdiag[a], pr = c_pair[a], ko = c_koff[a];
      u64 wd2[8], wp2[8], wsm2[16];
      load_wmv_row(m2_wmv, o, kd, ko, pr, wd2, wp2);
      if (a == 0){
        #pragma unroll
        for(int j=0;j<16;j++) wsm2[j] = pack2f(m2_wsm[o*32+2*j], m2_wsm[o*32+2*j+1]);
      }
      #pragma unroll
      for(int tt=0; tt<4; tt++){
        int t = tp + tt*4;
        float r0, r1;
        equi_mv_val2(SX2 + t*352, SX2 + (t+2)*352, a, pr, wd2, wp2, wsm2, r0, r1);
        SR[t*SRS + o*17 + a] += r0;
        SR[(t+2)*SRS + o*17 + a] += r1;
      }
    } else {
      int o = out - 256;
      u64 wss2[16], wms2[8];
      #pragma unroll
      for(int j=0;j<16;j++) wss2[j] = pack2f(m2_wss[o*32+2*j], m2_wss[o*32+2*j+1]);
      #pragma unroll
      for(int i=0;i<8;i++)  wms2[i] = pack2f(m2_wms[o*16+2*i], m2_wms[o*16+2*i+1]);
      #pragma unroll
      for(int tt=0; tt<4; tt++){
        int t = tp + tt*4;
        float r0, r1;
        equi_s_val2(SX2 + t*352, SX2 + (t+2)*352, wss2, wms2, r0, r1);
        SR[t*SRS + 272 + o] += r0;
        SR[(t+2)*SRS + 272 + o] += r1;
      }
    }
  }
  __syncthreads();

  // ---- stage 7+8: store residual; if FQ, also LN(SR) -> SX2 (both only
  // read SR, so no barrier needed between them) ----
  for(int idx=tid; idx<T*256; idx+=NT){
    int t = idx>>8, r = idx&255;
    g_mv[(t0+t)*256 + r] = SR[t*SRS + (r>>4)*17 + (r&15)];
  }
  for(int idx=tid; idx<T*32; idx+=NT){
    int t = idx>>5, j = idx&31;
    g_s[(t0+t)*32 + j] = SR[t*SRS + 272 + j];
  }

  if (!FQ) return;

  {
    int w = tid>>5, lane = tid&31;
    if (w < T){
      const float* R = SR + w*SRS;
      float ss = 0.f;
      #pragma unroll
      for(int r=0;r<8;r++){
        int li = lane + 32*r; int o = li>>4, a = li&15;
        float v = R[o*17 + a]; ss += v*v*c_inner[a];
      }
      #pragma unroll
      for(int off=16;off;off>>=1) ss += __shfl_xor_sync(0xffffffffu, ss, off);
      float sc = rsqrtf(ss*0.0625f + 1e-6f);
      #pragma unroll
      for(int r=0;r<8;r++){
        int li = lane + 32*r; int o = li>>4, a = li&15;
        SX2[w*352 + a*20 + o] = R[o*17 + a]*sc;
      }
      float v = R[272+lane];
      float s2 = v*v;
      #pragma unroll
      for(int off=16;off;off>>=1) s2 += __shfl_xor_sync(0xffffffffu, s2, off);
      SX2[w*352 + 320 + lane] = v * rsqrtf(s2*0.03125f + 1e-6f);
    }
  }
  __syncthreads();

  // ---- stage 9: next-layer QKV equi -> SH as SY (stride 864) ----
  for(int out = tid; out < 864; out += NT){
    if (out < 768){
      int o = out % 48, a = out / 48;
      int kd = c_kdiag[a], pr = c_pair[a], ko = c_koff[a];
      u64 wd2[8], wp2[8], wsm2[16];
      load_wmv_row(nq_wmv, o, kd, ko, pr, wd2, wp2);
      if (a == 0){
        #pragma unroll
        for(int j=0;j<16;j++) wsm2[j] = pack2f(nq_wsm[o*32+2*j], nq_wsm[o*32+2*j+1]);
      }
      for(int t=0; t<T; t+=2){
        float r0, r1;
        equi_mv_val2(SX2 + t*352, SX2 + (t+1)*352, a, pr, wd2, wp2, wsm2, r0, r1);
        SH[t*864 + a*48 + o] = r0;
        SH[(t+1)*864 + a*48 + o] = r1;
      }
    } else {
      int o = out - 768;  // 0..95
      u64 wss2[16], wms2[8];
      #pragma unroll
      for(int j=0;j<16;j++) wss2[j] = pack2f(nq_wss[o*32+2*j], nq_wss[o*32+2*j+1]);
      #pragma unroll
      for(int i=0;i<8;i++)  wms2[i] = pack2f(nq_wms[o*16+2*i], nq_wms[o*16+2*i+1]);
      for(int t=0; t<T; t+=2){
        float r0, r1;
        equi_s_val2(SX2 + t*352, SX2 + (t+1)*352, wss2, wms2, r0, r1);
        SH[t*864 + 768 + o] = r0;
        SH[(t+1)*864 + 768 + o] = r1;
      }
    }
  }
  __syncthreads();

  // ---- stage 10: pack Q/K/V ----
  for(int idx=tid; idx<8*T*20; idx+=NT){           // Q
    int h = idx/(T*20), rem = idx%(T*20), t = rem/20, e = rem%20;
    float v;
    if (e < 16){ int ci=e>>3, ib=e&7, a=c_iblades[ib]; v = SH[t*864 + a*48 + (h*2+ci)]; }
    else       { v = SH[t*864 + 768 + h*4 + (e-16)]; }
    g_Q[((size_t)(b*8+h)*NSEQ + n0 + t)*20 + e] = v;
  }
  for(int idx=tid; idx<8*T*20; idx+=NT){           // K
    int h = idx/(T*20), rem = idx%(T*20), t = rem/20, e = rem%20;
    float v;
    if (e < 16){ int ci=e>>3, ib=e&7, a=c_iblades[ib]; v = SH[t*864 + a*48 + (16 + h*2+ci)]; }
    else       { v = SH[t*864 + 768 + 32 + h*4 + (e-16)]; }
    g_K[((size_t)(b*8+h)*NSEQ + n0 + t)*20 + e] = v;
  }
  for(int idx=tid; idx<8*T*36; idx+=NT){           // V
    int h = idx/(T*36), rem = idx%(T*36), t = rem/36, e = rem%36;
    float v;
    if (e < 32){ int ci=e>>4, a=e&15; v = SH[t*864 + a*48 + (32 + h*2+ci)]; }
    else       { v = SH[t*864 + 768 + 64 + h*4 + (e-32)]; }
    g_V[((size_t)(b*8+h)*NSEQ + n0 + t)*36 + e] = v;
  }
}

// ---------------- final projection + mean ----------------
__global__ void final_kernel(const float* __restrict__ wout_mv,
                             const float* __restrict__ wout_sm,
                             float* __restrict__ out){
  int b = blockIdx.x, tid = threadIdx.x;
  __shared__ float red[256];
  float acc = 0.f;
  for(int n=tid; n<NSEQ; n+=256){
    size_t t = (size_t)b*NSEQ + n;
    const float* M = g_mv + t*256;
    const float* S = g_s + t*32;
    float v = 0.f;
    #pragma unroll
    for(int i=0;i<16;i++) v += wout_mv[i*9] * M[i*16];
    #pragma unroll
    for(int j=0;j<32;j++) v += wout_sm[j] * S[j];
    acc += v;
  }
  red[tid] = acc; __syncthreads();
  for(int s=128; s; s>>=1){ if (tid < s) red[tid] += red[tid+s]; __syncthreads(); }
  if (tid == 0) out[b] = red[0] * (1.f/NSEQ);
}

// ---------------- host ----------------
extern "C" void kernel_launch(void* const* d_in, const int* in_sizes, int n_in,
                              void* d_out, int out_size) {
  const float* inputs    = (const float*)d_in[0];
  const float* win_mv    = (const float*)d_in[1];
  const float* win_bs    = (const float*)d_in[3];
  const float* qkv_wmv   = (const float*)d_in[4];
  const float* qkv_wsm   = (const float*)d_in[5];
  const float* qkv_wms   = (const float*)d_in[6];
  const float* qkv_wss   = (const float*)d_in[7];
  const float* aout_wmv  = (const float*)d_in[8];
  const float* aout_wsm  = (const float*)d_in[9];
  const float* aout_wms  = (const float*)d_in[10];
  const float* aout_wss  = (const float*)d_in[11];
  const float* m1_wmv    = (const float*)d_in[12];
  const float* m1_wsm    = (const float*)d_in[13];
  const float* m1_wms    = (const float*)d_in[14];
  const float* m1_wss    = (const float*)d_in[15];
  const float* m2_wmv    = (const float*)d_in[16];
  const float* m2_wsm    = (const float*)d_in[17];
  const float* m2_wms    = (const float*)d_in[18];
  const float* m2_wss    = (const float*)d_in[19];
  const float* wout_mv   = (const float*)d_in[20];
  const float* wout_sm   = (const float*)d_in[21];

  const int smem_qkv  = (16*352 + 16*864) * 4;                        // 77824
  const int smem_blk  = (16*352 + 16*304 + 16*8*NSPLIT + 16*864) * 4; // 99328
  const int smem_attn = (2*640 + 2*1152) * 16;                        // 57344
  cudaFuncSetAttribute((const void*)qkv_kernel,
                       cudaFuncAttributeMaxDynamicSharedMemorySize, smem_qkv);
  cudaFuncSetAttribute((const void*)block2_kernel<true>,
                       cudaFuncAttributeMaxDynamicSharedMemorySize, smem_blk);
  cudaFuncSetAttribute((const void*)block2_kernel<false>,
                       cudaFuncAttributeMaxDynamicSharedMemorySize, smem_blk);
  cudaFuncSetAttribute((const void*)attn_kernel,
                       cudaFuncAttributeMaxDynamicSharedMemorySize, smem_attn);

  embed_kernel<<<(NTOK*48 + 255)/256, 256>>>(inputs, win_mv, win_bs);

  qkv_kernel<<<NTOK/16, 864, smem_qkv>>>(
      qkv_wmv, qkv_wsm, qkv_wms, qkv_wss);

  for (int l = 0; l < 8; l++){
    attn_kernel<<<dim3(64, NSEQ/256, NSPLIT), 128, smem_attn>>>();
    if (l < 7){
      int ln = l + 1;
      block2_kernel<true><<<NTOK/16, 576, smem_blk>>>(
          aout_wmv + (size_t)l*16*16*9, aout_wsm + (size_t)l*16*32,
          aout_wms + (size_t)l*32*16,   aout_wss + (size_t)l*32*32,
          m1_wmv  + (size_t)l*32*16*9,  m1_wsm  + (size_t)l*32*32,
          m1_wms  + (size_t)l*64*16,    m1_wss  + (size_t)l*64*32,
          m2_wmv  + (size_t)l*16*16*9,  m2_wsm  + (size_t)l*16*32,
          m2_wms  + (size_t)l*32*16,    m2_wss  + (size_t)l*32*32,
          qkv_wmv + (size_t)ln*48*16*9, qkv_wsm + (size_t)ln*48*32,
          qkv_wms + (size_t)ln*96*16,   qkv_wss + (size_t)ln*96*32);
    } else {
      block2_kernel<false><<<NTOK/16, 576, smem_blk>>>(
          aout_wmv + (size_t)l*16*16*9, aout_wsm + (size_t)l*16*32,
          aout_wms + (size_t)l*32*16,   aout_wss + (size_t)l*32*32,
          m1_wmv  + (size_t)l*32*16*9,  m1_wsm  + (size_t)l*32*32,
          m1_wms  + (size_t)l*64*16,    m1_wss  + (size_t)l*64*32,
          m2_wmv  + (size_t)l*16*16*9,  m2_wsm  + (size_t)l*16*32,
          m2_wms  + (size_t)l*32*16,    m2_wss  + (size_t)l*32*32,
          qkv_wmv, qkv_wsm, qkv_wms, qkv_wss);
    }
  }

  final_kernel<<<NBAT, 256>>>(wout_mv, wout_sm, (float*)d_out);
}

// round 15
// speedup vs baseline: 1.1386x; 1.0587x over previous
#include <cuda_runtime.h>
#include <math.h>

#define NTOK 8192
#define NSEQ 1024
#define NBAT 8
#define NSPLIT 4

typedef unsigned long long u64;

// ---------------- f32x2 packed helpers (Blackwell) ----------------
__device__ __forceinline__ u64 pack2f(float lo, float hi){
  u64 r; asm("mov.b64 %0, {%1, %2};" : "=l"(r) : "f"(lo), "f"(hi)); return r;
}
__device__ __forceinline__ u64 ffma2(u64 a, u64 b, u64 c){
  u64 d; asm("fma.rn.f32x2 %0, %1, %2, %3;" : "=l"(d) : "l"(a), "l"(b), "l"(c)); return d;
}
__device__ __forceinline__ u64 fmul2(u64 a, u64 b){
  u64 d; asm("mul.rn.f32x2 %0, %1, %2;" : "=l"(d) : "l"(a), "l"(b)); return d;
}
__device__ __forceinline__ u64 fadd2(u64 a, u64 b){
  u64 d; asm("add.rn.f32x2 %0, %1, %2;" : "=l"(d) : "l"(a), "l"(b)); return d;
}
__device__ __forceinline__ float hadd2(u64 v){
  float a,b; asm("mov.b64 {%0, %1}, %2;" : "=f"(a), "=f"(b) : "l"(v)); return a+b;
}
__device__ __forceinline__ u64 lo2(float4 v){ return pack2f(v.x, v.y); }
__device__ __forceinline__ u64 hi2(float4 v){ return pack2f(v.z, v.w); }
// ---------------- cp.async helpers ----------------
__device__ __forceinline__ void cpa16(void* s, const void* g){
  unsigned sa = (unsigned)__cvta_generic_to_shared(s);
  asm volatile("cp.async.cg.shared.global [%0], [%1], 16;" :: "r"(sa), "l"(g));
}
__device__ __forceinline__ void cpa_commit(){ asm volatile("cp.async.commit_group;"); }
__device__ __forceinline__ void cpa_wait0(){ asm volatile("cp.async.wait_group 0;"); }

// ---------------- device scratch ----------------
__device__ float g_mv [NTOK*256];
__device__ float g_s  [NTOK*32];
__device__ float g_Q[(size_t)64*NSEQ*20];
__device__ float g_K[(size_t)64*NSEQ*20];
__device__ float g_V[(size_t)64*NSEQ*36];
__device__ float g_Osp[(size_t)64*NSEQ*NSPLIT*38];   // [bh][n][split][36 acc + m + l]

// ---------------- blade tables ----------------
__constant__ int   c_kdiag[16] = {0,1,1,1,1,2,2,2,2,2,2,3,3,3,3,4};
__constant__ int   c_pair [16] = {-1,0,-1,-1,-1,2,3,4,-1,-1,-1,8,9,10,-1,14};
__constant__ int   c_koff [16] = {0,5,0,0,0,6,6,6,0,0,0,7,7,7,0,8};
__constant__ float c_inner[16] = {1,0,1,1,1,0,0,0,1,1,1,0,0,0,1,0};
__constant__ int   c_iblades[8]= {0,2,3,4,8,9,10,14};

// compile-time blade algebra (geometric product)
__host__ __device__ constexpr int blade_mask(int i){
  return i==0?0: i==1?1: i==2?2: i==3?4: i==4?8: i==5?3: i==6?5: i==7?9:
         i==8?6: i==9?10: i==10?12: i==11?7: i==12?11: i==13?13: i==14?14: 15;
}
__host__ __device__ constexpr int mask_idx(int m){
  return m==0?0: m==1?1: m==2?2: m==3?5: m==4?3: m==5?6: m==6?8: m==7?11:
         m==8?4: m==9?7: m==10?9: m==11?12: m==12?10: m==13?13: m==14?14: 15;
}
__host__ __device__ constexpr int pc4(int v){ return (v&1)+((v>>1)&1)+((v>>2)&1)+((v>>3)&1); }
__host__ __device__ constexpr int gp_par(int ma,int mb){
  return ( ((mb&1)?pc4(ma>>1):0) + (((mb>>1)&1)?pc4(ma>>2):0) + (((mb>>2)&1)?pc4(ma>>3):0) ) & 1;
}
template<int I,int J>
__device__ __forceinline__ void gp_term(float (&acc)[16], const float* x, const float* y){
  constexpr int ma = blade_mask(I);
  constexpr int mb = blade_mask(J);
  if constexpr (!(ma & mb & 1)) {
    constexpr int k  = mask_idx(ma ^ mb);
    constexpr int sg = gp_par(ma, mb);
    float p = x[I]*y[J];
    if constexpr (sg) acc[k] -= p; else acc[k] += p;
  }
}
#define GP_ROW(I) \
  gp_term<I,0>(acc,x,y);  gp_term<I,1>(acc,x,y);  gp_term<I,2>(acc,x,y);  gp_term<I,3>(acc,x,y); \
  gp_term<I,4>(acc,x,y);  gp_term<I,5>(acc,x,y);  gp_term<I,6>(acc,x,y);  gp_term<I,7>(acc,x,y); \
  gp_term<I,8>(acc,x,y);  gp_term<I,9>(acc,x,y);  gp_term<I,10>(acc,x,y); gp_term<I,11>(acc,x,y);\
  gp_term<I,12>(acc,x,y); gp_term<I,13>(acc,x,y); gp_term<I,14>(acc,x,y); gp_term<I,15>(acc,x,y);

__device__ __forceinline__ float gelu_f(float v){
  float v3 = v*v*v;
  return 0.5f*v*(1.f + tanhf(0.7978845608028654f*(v + 0.044715f*v3)));
}

// ---- equi building blocks: TWO tokens per call, float4 (LDS.128) loads ----
__device__ __forceinline__ void load_wmv_row(const float* wmv, int o, int kd, int ko, int pr,
                                             u64* wd2, u64* wp2){
  #pragma unroll
  for(int i=0;i<8;i++)
    wd2[i] = pack2f(wmv[o*144 + (2*i)*9 + kd], wmv[o*144 + (2*i+1)*9 + kd]);
  if (pr >= 0){
    #pragma unroll
    for(int i=0;i<8;i++)
      wp2[i] = pack2f(wmv[o*144 + (2*i)*9 + ko], wmv[o*144 + (2*i+1)*9 + ko]);
  }
}
__device__ __forceinline__ void equi_mv_val2(const float* X0, const float* X1, int a, int pr,
    const u64* wd2, const u64* wp2, const u64* wsm2, float& r0, float& r1){
  const float4* A0 = (const float4*)(X0 + a*20);
  const float4* A1 = (const float4*)(X1 + a*20);
  u64 p0, p1, q0, q1;
  {
    float4 f0 = A0[0], f1 = A0[1], g0 = A1[0], g1 = A1[1];
    p0 = fmul2(wd2[0], lo2(f0)); p1 = fmul2(wd2[1], hi2(f0));
    q0 = fmul2(wd2[0], lo2(g0)); q1 = fmul2(wd2[1], hi2(g0));
    p0 = ffma2(wd2[2], lo2(f1), p0); p1 = ffma2(wd2[3], hi2(f1), p1);
    q0 = ffma2(wd2[2], lo2(g1), q0); q1 = ffma2(wd2[3], hi2(g1), q1);
    float4 f2 = A0[2], f3 = A0[3], g2 = A1[2], g3 = A1[3];
    p0 = ffma2(wd2[4], lo2(f2), p0); p1 = ffma2(wd2[5], hi2(f2), p1);
    q0 = ffma2(wd2[4], lo2(g2), q0); q1 = ffma2(wd2[5], hi2(g2), q1);
    p0 = ffma2(wd2[6], lo2(f3), p0); p1 = ffma2(wd2[7], hi2(f3), p1);
    q0 = ffma2(wd2[6], lo2(g3), q0); q1 = ffma2(wd2[7], hi2(g3), q1);
  }
  if (pr >= 0){
    const float4* B0 = (const float4*)(X0 + pr*20);
    const float4* B1 = (const float4*)(X1 + pr*20);
    float4 f0 = B0[0], f1 = B0[1], g0 = B1[0], g1 = B1[1];
    p0 = ffma2(wp2[0], lo2(f0), p0); p1 = ffma2(wp2[1], hi2(f0), p1);
    q0 = ffma2(wp2[0], lo2(g0), q0); q1 = ffma2(wp2[1], hi2(g0), q1);
    p0 = ffma2(wp2[2], lo2(f1), p0); p1 = ffma2(wp2[3], hi2(f1), p1);
    q0 = ffma2(wp2[2], lo2(g1), q0); q1 = ffma2(wp2[3], hi2(g1), q1);
    float4 f2 = B0[2], f3 = B0[3], g2 = B1[2], g3 = B1[3];
    p0 = ffma2(wp2[4], lo2(f2), p0); p1 = ffma2(wp2[5], hi2(f2), p1);
    q0 = ffma2(wp2[4], lo2(g2), q0); q1 = ffma2(wp2[5], hi2(g2), q1);
    p0 = ffma2(wp2[6], lo2(f3), p0); p1 = ffma2(wp2[7], hi2(f3), p1);
    q0 = ffma2(wp2[6], lo2(g3), q0); q1 = ffma2(wp2[7], hi2(g3), q1);
  }
  if (a == 0){
    const float4* S0 = (const float4*)(X0 + 320);
    const float4* S1 = (const float4*)(X1 + 320);
    #pragma unroll
    for(int c=0;c<8;c++){
      float4 f = S0[c], g = S1[c];
      p0 = ffma2(wsm2[2*c], lo2(f), p0); p1 = ffma2(wsm2[2*c+1], hi2(f), p1);
      q0 = ffma2(wsm2[2*c], lo2(g), q0); q1 = ffma2(wsm2[2*c+1], hi2(g), q1);
    }
  }
  r0 = hadd2(fadd2(p0, p1));
  r1 = hadd2(fadd2(q0, q1));
}
__device__ __forceinline__ void equi_s_val2(const float* X0, const float* X1,
    const u64* wss2, const u64* wms2, float& r0, float& r1){
  const float4* S0 = (const float4*)(X0 + 320);
  const float4* S1 = (const float4*)(X1 + 320);
  u64 p0, p1, q0, q1;
  {
    float4 f = S0[0], g = S1[0];
    p0 = fmul2(wss2[0], lo2(f)); p1 = fmul2(wss2[1], hi2(f));
    q0 = fmul2(wss2[0], lo2(g)); q1 = fmul2(wss2[1], hi2(g));
  }
  #pragma unroll
  for(int c=1;c<8;c++){
    float4 f = S0[c], g = S1[c];
    p0 = ffma2(wss2[2*c], lo2(f), p0); p1 = ffma2(wss2[2*c+1], hi2(f), p1);
    q0 = ffma2(wss2[2*c], lo2(g), q0); q1 = ffma2(wss2[2*c+1], hi2(g), q1);
  }
  const float4* Z0 = (const float4*)(X0);
  const float4* Z1 = (const float4*)(X1);
  #pragma unroll
  for(int c=0;c<4;c++){
    float4 f = Z0[c], g = Z1[c];
    p0 = ffma2(wms2[2*c], lo2(f), p0); p1 = ffma2(wms2[2*c+1], hi2(f), p1);
    q0 = ffma2(wms2[2*c], lo2(g), q0); q1 = ffma2(wms2[2*c+1], hi2(g), q1);
  }
  r0 = hadd2(fadd2(p0, p1));
  r1 = hadd2(fadd2(q0, q1));
}

// ---------------- embed ----------------
__global__ void embed_kernel(const float* __restrict__ inp,
                             const float* __restrict__ win_mv,
                             const float* __restrict__ win_bs){
  int idx = blockIdx.x*blockDim.x + threadIdx.x;
  if (idx < NTOK*16){
    int t = idx>>4, o = idx&15;
    float x = inp[t*3+0], y = inp[t*3+1], z = inp[t*3+2];
    float w3 = win_mv[o*9+3], w8 = win_mv[o*9+8];
    float* M = g_mv + (size_t)t*256 + o*16;
    #pragma unroll
    for(int a=0;a<16;a++) M[a]=0.f;
    M[11] = -z*w3;  M[12] = y*w3;  M[13] = -x*w3;  M[14] = w3;  M[15] = w8;
  } else if (idx < NTOK*16 + NTOK*32){
    int r = idx - NTOK*16; int t = r>>5, j = r&31;
    g_s[t*32+j] = win_bs[j];
  }
}

// ---------------- LN + QKV equi, staged coalesced pack (layer 0 only) ------
__global__ void __launch_bounds__(864) qkv_kernel(
    const float* __restrict__ wmv, const float* __restrict__ wsm,
    const float* __restrict__ wms, const float* __restrict__ wss)
{
  constexpr int T = 16, NT = 864;
  extern __shared__ float sm[];
  float* SX = sm;            // T*352
  float* SY = sm + T*352;    // T*864
  const int tid = threadIdx.x;
  const size_t t0 = (size_t)blockIdx.x * T;
  const int b = (int)(t0 >> 10), n0 = (int)(t0 & 1023);

  for(int idx=tid; idx<T*256; idx+=NT){
    int t = idx>>8, r = idx&255, i = r>>4, a = r&15;
    SX[t*352 + a*20 + i] = g_mv[(t0+t)*256 + r];
  }
  for(int idx=tid; idx<T*32; idx+=NT){
    int t = idx>>5, j = idx&31;
    SX[t*352 + 320 + j] = g_s[(t0+t)*32 + j];
  }
  __syncthreads();

  { // LN: warp w -> token w
    int w = tid>>5, lane = tid&31;
    if (w < T){
      float* X = SX + w*352;
      int a = lane>>1;
      int base = a*20 + (lane&1)*8;
      float msk = c_inner[a];
      float ss = 0.f;
      #pragma unroll
      for(int r=0;r<8;r++){ float v = X[base+r]; ss += v*v*msk; }
      #pragma unroll
      for(int off=16;off;off>>=1) ss += __shfl_xor_sync(0xffffffffu, ss, off);
      float sc = rsqrtf(ss*0.0625f + 1e-6f);
      #pragma unroll
      for(int r=0;r<8;r++) X[base+r] *= sc;
      float v = X[320+lane];
      float s2 = v*v;
      #pragma unroll
      for(int off=16;off;off>>=1) s2 += __shfl_xor_sync(0xffffffffu, s2, off);
      X[320+lane] = v * rsqrtf(s2*0.03125f + 1e-6f);
    }
  }
  __syncthreads();

  if (tid < 768){
    int o = tid % 48, a = tid / 48;
    int kd = c_kdiag[a], pr = c_pair[a], ko = c_koff[a];
    u64 wd2[8], wp2[8], wsm2[16];
    load_wmv_row(wmv, o, kd, ko, pr, wd2, wp2);
    if (a == 0){
      #pragma unroll
      for(int j=0;j<16;j++) wsm2[j] = pack2f(wsm[o*32+2*j], wsm[o*32+2*j+1]);
    }
    for(int t=0; t<T; t+=2){
      float r0, r1;
      equi_mv_val2(SX + t*352, SX + (t+1)*352, a, pr, wd2, wp2, wsm2, r0, r1);
      SY[t*864 + a*48 + o] = r0;
      SY[(t+1)*864 + a*48 + o] = r1;
    }
  } else {
    int o = tid - 768;  // 0..95
    u64 wss2[16], wms2[8];
    #pragma unroll
    for(int j=0;j<16;j++) wss2[j] = pack2f(wss[o*32+2*j], wss[o*32+2*j+1]);
    #pragma unroll
    for(int i=0;i<8;i++)  wms2[i] = pack2f(wms[o*16+2*i], wms[o*16+2*i+1]);
    for(int t=0; t<T; t+=2){
      float r0, r1;
      equi_s_val2(SX + t*352, SX + (t+1)*352, wss2, wms2, r0, r1);
      SY[t*864 + 768 + o] = r0;
      SY[(t+1)*864 + 768 + o] = r1;
    }
  }
  __syncthreads();

  for(int idx=tid; idx<8*T*20; idx+=NT){           // Q
    int h = idx/(T*20), rem = idx%(T*20), t = rem/20, e = rem%20;
    float v;
    if (e < 16){ int ci=e>>3, ib=e&7, a=c_iblades[ib]; v = SY[t*864 + a*48 + (h*2+ci)]; }
    else       { v = SY[t*864 + 768 + h*4 + (e-16)]; }
    g_Q[((size_t)(b*8+h)*NSEQ + n0 + t)*20 + e] = v;
  }
  for(int idx=tid; idx<8*T*20; idx+=NT){           // K
    int h = idx/(T*20), rem = idx%(T*20), t = rem/20, e = rem%20;
    float v;
    if (e < 16){ int ci=e>>3, ib=e&7, a=c_iblades[ib]; v = SY[t*864 + a*48 + (16 + h*2+ci)]; }
    else       { v = SY[t*864 + 768 + 32 + h*4 + (e-16)]; }
    g_K[((size_t)(b*8+h)*NSEQ + n0 + t)*20 + e] = v;
  }
  for(int idx=tid; idx<8*T*36; idx+=NT){           // V
    int h = idx/(T*36), rem = idx%(T*36), t = rem/36, e = rem%36;
    float v;
    if (e < 32){ int ci=e>>4, a=e&15; v = SY[t*864 + a*48 + (32 + h*2+ci)]; }
    else       { v = SY[t*864 + 768 + 64 + h*4 + (e-32)]; }
    g_V[((size_t)(b*8+h)*NSEQ + n0 + t)*36 + e] = v;
  }
}

// ---------------- attention (split-KV x4, 2 q/thread, 128-key tiles) -------
__global__ void __launch_bounds__(128) attn_kernel(){
  const int bh = blockIdx.x, qt = blockIdx.y, z = blockIdx.z, tid = threadIdx.x;
  const int qi0 = qt*256 + tid;
  const float SCALE = 0.22360679774997896f;  // 1/sqrt(20)

  extern __shared__ float4 dyn4[];
  float4* sk4 = dyn4;            // 2 x 640
  float4* sv4 = dyn4 + 1280;     // 2 x 1152

  u64 q0[10], q1[10];
  {
    const float* qp0 = g_Q + ((size_t)bh*NSEQ + qi0)*20;
    const float* qp1 = qp0 + 128*20;
    #pragma unroll
    for(int c=0;c<10;c++){
      q0[c] = pack2f(qp0[2*c]*SCALE, qp0[2*c+1]*SCALE);
      q1[c] = pack2f(qp1[2*c]*SCALE, qp1[2*c+1]*SCALE);
    }
  }
  float m0=-1e30f, l0=0.f, m1=-1e30f, l1=0.f;
  u64 a0[18], a1[18];
  #pragma unroll
  for(int c=0;c<18;c++){ a0[c]=0ull; a1[c]=0ull; }

  const int kt0 = z*2;
  const float4* kp = (const float4*)(g_K + (size_t)bh*NSEQ*20) + kt0*128*5;
  const float4* vp = (const float4*)(g_V + (size_t)bh*NSEQ*36) + kt0*128*9;

  #pragma unroll
  for(int i=0;i<5;i++) cpa16(&sk4[tid + 128*i], &kp[tid + 128*i]);
  #pragma unroll
  for(int i=0;i<9;i++) cpa16(&sv4[tid + 128*i], &vp[tid + 128*i]);
  cpa_commit();
  cpa_wait0();
  __syncthreads();

  for(int ki=0; ki<2; ki++){
    const int cur = ki & 1, nxt = cur ^ 1;
    if (ki < 1){
      const float4* kpn = kp + 128*5;
      const float4* vpn = vp + 128*9;
      #pragma unroll
      for(int i=0;i<5;i++) cpa16(&sk4[nxt*640 + tid + 128*i], &kpn[tid + 128*i]);
      #pragma unroll
      for(int i=0;i<9;i++) cpa16(&sv4[nxt*1152 + tid + 128*i], &vpn[tid + 128*i]);
      cpa_commit();
    }
    const float4* skc = sk4 + cur*640;
    const float4* svc = sv4 + cur*1152;

    #pragma unroll 2
    for(int j=0; j<128; j++){
      const float4* kk4 = skc + j*5;
      float4 k0 = kk4[0], k1 = kk4[1], k2 = kk4[2], k3 = kk4[3], k4 = kk4[4];
      u64 t0a = fmul2(q0[0], lo2(k0)), t0b = fmul2(q0[1], hi2(k0));
      u64 t1a = fmul2(q1[0], lo2(k0)), t1b = fmul2(q1[1], hi2(k0));
      t0a = ffma2(q0[2], lo2(k1), t0a); t0b = ffma2(q0[3], hi2(k1), t0b);
      t1a = ffma2(q1[2], lo2(k1), t1a); t1b = ffma2(q1[3], hi2(k1), t1b);
      t0a = ffma2(q0[4], lo2(k2), t0a); t0b = ffma2(q0[5], hi2(k2), t0b);
      t1a = ffma2(q1[4], lo2(k2), t1a); t1b = ffma2(q1[5], hi2(k2), t1b);
      t0a = ffma2(q0[6], lo2(k3), t0a); t0b = ffma2(q0[7], hi2(k3), t0b);
      t1a = ffma2(q1[6], lo2(k3), t1a); t1b = ffma2(q1[7], hi2(k3), t1b);
      t0a = ffma2(q0[8], lo2(k4), t0a); t0b = ffma2(q0[9], hi2(k4), t0b);
      t1a = ffma2(q1[8], lo2(k4), t1a); t1b = ffma2(q1[9], hi2(k4), t1b);
      float s0 = hadd2(fadd2(t0a, t0b));
      float s1 = hadd2(fadd2(t1a, t1b));
      float p0, p1;
      if (s0 > m0){
        float cc = __expf(m0 - s0); m0 = s0; l0 = l0*cc + 1.f;
        u64 cp = pack2f(cc, cc);
        #pragma unroll
        for(int c=0;c<18;c++) a0[c] = fmul2(a0[c], cp);
        p0 = 1.f;
      } else { p0 = __expf(s0 - m0); l0 += p0; }
      if (s1 > m1){
        float cc = __expf(m1 - s1); m1 = s1; l1 = l1*cc + 1.f;
        u64 cp = pack2f(cc, cc);
        #pragma unroll
        for(int c=0;c<18;c++) a1[c] = fmul2(a1[c], cp);
        p1 = 1.f;
      } else { p1 = __expf(s1 - m1); l1 += p1; }
      u64 pp0 = pack2f(p0, p0), pp1 = pack2f(p1, p1);
      const float4* vv4 = svc + j*9;
      #pragma unroll
      for(int i=0;i<9;i++){
        float4 v4 = vv4[i];
        u64 vl = lo2(v4), vh = hi2(v4);
        a0[2*i]   = ffma2(pp0, vl, a0[2*i]);
        a0[2*i+1] = ffma2(pp0, vh, a0[2*i+1]);
        a1[2*i]   = ffma2(pp1, vl, a1[2*i]);
        a1[2*i+1] = ffma2(pp1, vh, a1[2*i+1]);
      }
    }
    if (ki < 1){
      cpa_wait0();
      __syncthreads();
    }
  }
  float* op0 = g_Osp + ((size_t)(bh*NSEQ + qi0)*NSPLIT + z)*38;
  float* op1 = g_Osp + ((size_t)(bh*NSEQ + qi0 + 128)*NSPLIT + z)*38;
  #pragma unroll
  for(int c=0;c<18;c++){
    ((u64*)op0)[c] = a0[c];
    ((u64*)op1)[c] = a1[c];
  }
  op0[36] = m0; op0[37] = l0;
  op1[36] = m1; op1[37] = l1;
}

// ---- fused: merge + out-proj + res + LN + mlp1 + GP + mlp2 + res (+ next QKV)
// NT=320 with 2 resident blocks/SM (regs 2*320*96 < 64K, smem 2*97KB < 228KB)
template<bool FQ>
__global__ void __launch_bounds__(320, 2) block2_kernel(
    const float* __restrict__ ao_wmv, const float* __restrict__ ao_wsm,
    const float* __restrict__ ao_wms, const float* __restrict__ ao_wss,
    const float* __restrict__ m1_wmv, const float* __restrict__ m1_wsm,
    const float* __restrict__ m1_wms, const float* __restrict__ m1_wss,
    const float* __restrict__ m2_wmv, const float* __restrict__ m2_wsm,
    const float* __restrict__ m2_wms, const float* __restrict__ m2_wss,
    const float* __restrict__ nq_wmv, const float* __restrict__ nq_wsm,
    const float* __restrict__ nq_wms, const float* __restrict__ nq_wss)
{
  constexpr int T = 16, NT = 320, SRS = 304;
  extern __shared__ float sm[];
  float* SA  = sm;                 // T*352  attn-out (blade-major); later SX2
  float* SR  = SA + T*352;         // T*304  residual [o*17+a], scalars at 272
  float* SW  = SR + T*SRS;         // T*8*NSPLIT merge weights
  float* SH  = SW + T*8*NSPLIT;    // T*864 region: mlp1 hidden (608) / qkv SY (864)
  float* SX2 = SA;
  const int tid = threadIdx.x;
  const size_t t0 = (size_t)blockIdx.x * T;
  const int b = (int)(t0 >> 10), n0 = (int)(t0 & 1023);

  // ---- stage 0: merge weights + residual loads ----
  if (tid < T*8){
    int t = tid>>3, h = tid&7;
    const float* p = g_Osp + (((size_t)(b*8+h)*NSEQ + n0 + t)*NSPLIT)*38;
    float m[NSPLIT], l[NSPLIT];
    float mm = -1e30f;
    #pragma unroll
    for(int z=0;z<NSPLIT;z++){ m[z]=p[z*38+36]; l[z]=p[z*38+37]; mm = fmaxf(mm, m[z]); }
    float den = 0.f, w[NSPLIT];
    #pragma unroll
    for(int z=0;z<NSPLIT;z++){ w[z] = __expf(m[z]-mm); den += l[z]*w[z]; }
    float inv = 1.f/den;
    #pragma unroll
    for(int z=0;z<NSPLIT;z++) SW[tid*NSPLIT + z] = w[z]*inv;
  }
  for(int idx=tid; idx<T*256; idx+=NT){
    int t = idx>>8, r = idx&255;
    SR[t*SRS + (r>>4)*17 + (r&15)] = g_mv[(t0+t)*256 + r];
  }
  for(int idx=tid; idx<T*32; idx+=NT){
    int t = idx>>5, j = idx&31;
    SR[t*SRS + 272 + j] = g_s[(t0+t)*32 + j];
  }
  __syncthreads();

  // ---- stage 1: merged attn-out -> SA (blade-major) ----
  for(int idx=tid; idx<T*288; idx+=NT){
    int t = idx/288, r = idx%288;
    int h = r/36, e = r%36;
    const float* p = g_Osp + (((size_t)(b*8+h)*NSEQ + n0 + t)*NSPLIT)*38;
    const float* wv = SW + (t*8+h)*NSPLIT;
    float v = 0.f;
    #pragma unroll
    for(int z=0;z<NSPLIT;z++) v += p[z*38 + e] * wv[z];
    if (e < 32){ int ci=e>>4, a=e&15; SA[t*352 + a*20 + (h*2+ci)] = v; }
    else       { SA[t*352 + 320 + h*4 + (e-32)] = v; }
  }
  __syncthreads();

  // ---- stage 2: out-projection equi + residual add into SR ----
  if (tid < 288){
    int out = tid;
    if (out < 256){
      int o = out & 15, a = out >> 4;
      int kd = c_kdiag[a], pr = c_pair[a], ko = c_koff[a];
      u64 wd2[8], wp2[8], wsm2[16];
      load_wmv_row(ao_wmv, o, kd, ko, pr, wd2, wp2);
      if (a == 0){
        #pragma unroll
        for(int j=0;j<16;j++) wsm2[j] = pack2f(ao_wsm[o*32+2*j], ao_wsm[o*32+2*j+1]);
      }
      #pragma unroll
      for(int t=0; t<T; t+=2){
        float r0, r1;
        equi_mv_val2(SA + t*352, SA + (t+1)*352, a, pr, wd2, wp2, wsm2, r0, r1);
        SR[t*SRS + o*17 + a] += r0;
        SR[(t+1)*SRS + o*17 + a] += r1;
      }
    } else {
      int o = out - 256;
      u64 wss2[16], wms2[8];
      #pragma unroll
      for(int j=0;j<16;j++) wss2[j] = pack2f(ao_wss[o*32+2*j], ao_wss[o*32+2*j+1]);
      #pragma unroll
      for(int i=0;i<8;i++)  wms2[i] = pack2f(ao_wms[o*16+2*i], ao_wms[o*16+2*i+1]);
      #pragma unroll
      for(int t=0; t<T; t+=2){
        float r0, r1;
        equi_s_val2(SA + t*352, SA + (t+1)*352, wss2, wms2, r0, r1);
        SR[t*SRS + 272 + o] += r0;
        SR[(t+1)*SRS + 272 + o] += r1;
      }
    }
  }
  __syncthreads();

  // ---- stage 3: LN(SR) -> SX2 ----
  for(int w = tid>>5; w < T; w += NT/32){
    int lane = tid&31;
    const float* R = SR + w*SRS;
    float ss = 0.f;
    #pragma unroll
    for(int r=0;r<8;r++){
      int li = lane + 32*r; int o = li>>4, a = li&15;
      float v = R[o*17 + a]; ss += v*v*c_inner[a];
    }
    #pragma unroll
    for(int off=16;off;off>>=1) ss += __shfl_xor_sync(0xffffffffu, ss, off);
    float sc = rsqrtf(ss*0.0625f + 1e-6f);
    #pragma unroll
    for(int r=0;r<8;r++){
      int li = lane + 32*r; int o = li>>4, a = li&15;
      SX2[w*352 + a*20 + o] = R[o*17 + a]*sc;
    }
    float v = R[272+lane];
    float s2 = v*v;
    #pragma unroll
    for(int off=16;off;off>>=1) s2 += __shfl_xor_sync(0xffffffffu, s2, off);
    SX2[w*352 + 320 + lane] = v * rsqrtf(s2*0.03125f + 1e-6f);
  }
  __syncthreads();

  // ---- stage 4: mlp1 equi (512 mv + 64 s outs over 2 passes) -> SH ----
  #pragma unroll
  for(int pass=0; pass<2; pass++){
    int out = tid + pass*NT;
    if (out < 512){
      int o = out % 32, a = out / 32;
      int kd = c_kdiag[a], pr = c_pair[a], ko = c_koff[a];
      u64 wd2[8], wp2[8], wsm2[16];
      load_wmv_row(m1_wmv, o, kd, ko, pr, wd2, wp2);
      if (a == 0){
        #pragma unroll
        for(int j=0;j<16;j++) wsm2[j] = pack2f(m1_wsm[o*32+2*j], m1_wsm[o*32+2*j+1]);
      }
      #pragma unroll
      for(int t=0; t<T; t+=2){
        float r0, r1;
        equi_mv_val2(SX2 + t*352, SX2 + (t+1)*352, a, pr, wd2, wp2, wsm2, r0, r1);
        SH[t*608 + o*17 + a] = r0;
        SH[(t+1)*608 + o*17 + a] = r1;
      }
    } else if (out < 576){
      int o = out - 512;  // 0..63
      u64 wss2[16], wms2[8];
      #pragma unroll
      for(int j=0;j<16;j++) wss2[j] = pack2f(m1_wss[o*32+2*j], m1_wss[o*32+2*j+1]);
      #pragma unroll
      for(int i=0;i<8;i++)  wms2[i] = pack2f(m1_wms[o*16+2*i], m1_wms[o*16+2*i+1]);
      #pragma unroll
      for(int t=0; t<T; t+=2){
        float r0, r1;
        equi_s_val2(SX2 + t*352, SX2 + (t+1)*352, wss2, wms2, r0, r1);
        SH[t*608 + 544 + o] = r0;
        SH[(t+1)*608 + 544 + o] = r1;
      }
    }
  }
  __syncthreads();

  // ---- stage 5: geometric product + gated gelu -> SX2 ----
  for(int idx=tid; idx<T*48; idx+=NT){
    if (idx < T*16){
      int t = idx>>4, c = idx&15;
      const float* h1 = SH + t*608 + c*17;
      const float* h2 = SH + t*608 + (16+c)*17;
      float x[16], y[16], acc[16];
      #pragma unroll
      for(int i=0;i<16;i++){ x[i]=h1[i]; y[i]=h2[i]; acc[i]=0.f; }
      GP_ROW(0)  GP_ROW(1)  GP_ROW(2)  GP_ROW(3)
      GP_ROW(4)  GP_ROW(5)  GP_ROW(6)  GP_ROW(7)
      GP_ROW(8)  GP_ROW(9)  GP_ROW(10) GP_ROW(11)
      GP_ROW(12) GP_ROW(13) GP_ROW(14) GP_ROW(15)
      float g = gelu_f(acc[0]);
      #pragma unroll
      for(int a=0;a<16;a++) SX2[t*352 + a*20 + c] = acc[a]*g;
    } else {
      int r = idx - T*16; int t = r>>5, j = r&31;
      const float* hs = SH + t*608 + 544;
      SX2[t*352 + 320 + j] = hs[j] * gelu_f(hs[32+j]);
    }
  }
  __syncthreads();

  // ---- stage 6: mlp2 equi + residual add into SR ----
  if (tid < 288){
    int out = tid;
    if (out < 256){
      int o = out & 15, a = out >> 4;
      int kd = c_kdiag[a], pr = c_pair[a], ko = c_koff[a];
      u64 wd2[8], wp2[8], wsm2[16];
      load_wmv_row(m2_wmv, o, kd, ko, pr, wd2, wp2);
      if (a == 0){
        #pragma unroll
        for(int j=0;j<16;j++) wsm2[j] = pack2f(m2_wsm[o*32+2*j], m2_wsm[o*32+2*j+1]);
      }
      #pragma unroll
      for(int t=0; t<T; t+=2){
        float r0, r1;
        equi_mv_val2(SX2 + t*352, SX2 + (t+1)*352, a, pr, wd2, wp2, wsm2, r0, r1);
        SR[t*SRS + o*17 + a] += r0;
        SR[(t+1)*SRS + o*17 + a] += r1;
      }
    } else {
      int o = out - 256;
      u64 wss2[16], wms2[8];
      #pragma unroll
      for(int j=0;j<16;j++) wss2[j] = pack2f(m2_wss[o*32+2*j], m2_wss[o*32+2*j+1]);
      #pragma unroll
      for(int i=0;i<8;i++)  wms2[i] = pack2f(m2_wms[o*16+2*i], m2_wms[o*16+2*i+1]);
      #pragma unroll
      for(int t=0; t<T; t+=2){
        float r0, r1;
        equi_s_val2(SX2 + t*352, SX2 + (t+1)*352, wss2, wms2, r0, r1);
        SR[t*SRS + 272 + o] += r0;
        SR[(t+1)*SRS + 272 + o] += r1;
      }
    }
  }
  __syncthreads();

  // ---- stage 7+8: store residual; if FQ, also LN(SR) -> SX2 ----
  for(int idx=tid; idx<T*256; idx+=NT){
    int t = idx>>8, r = idx&255;
    g_mv[(t0+t)*256 + r] = SR[t*SRS + (r>>4)*17 + (r&15)];
  }
  for(int idx=tid; idx<T*32; idx+=NT){
    int t = idx>>5, j = idx&31;
    g_s[(t0+t)*32 + j] = SR[t*SRS + 272 + j];
  }

  if (!FQ) return;

  for(int w = tid>>5; w < T; w += NT/32){
    int lane = tid&31;
    const float* R = SR + w*SRS;
    float ss = 0.f;
    #pragma unroll
    for(int r=0;r<8;r++){
      int li = lane + 32*r; int o = li>>4, a = li&15;
      float v = R[o*17 + a]; ss += v*v*c_inner[a];
    }
    #pragma unroll
    for(int off=16;off;off>>=1) ss += __shfl_xor_sync(0xffffffffu, ss, off);
    float sc = rsqrtf(ss*0.0625f + 1e-6f);
    #pragma unroll
    for(int r=0;r<8;r++){
      int li = lane + 32*r; int o = li>>4, a = li&15;
      SX2[w*352 + a*20 + o] = R[o*17 + a]*sc;
    }
    float v = R[272+lane];
    float s2 = v*v;
    #pragma unroll
    for(int off=16;off;off>>=1) s2 += __shfl_xor_sync(0xffffffffu, s2, off);
    SX2[w*352 + 320 + lane] = v * rsqrtf(s2*0.03125f + 1e-6f);
  }
  __syncthreads();

  // ---- stage 9: next-layer QKV equi -> SH as SY (stride 864) ----
  for(int out = tid; out < 864; out += NT){
    if (out < 768){
      int o = out % 48, a = out / 48;
      int kd = c_kdiag[a], pr = c_pair[a], ko = c_koff[a];
      u64 wd2[8], wp2[8], wsm2[16];
      load_wmv_row(nq_wmv, o, kd, ko, pr, wd2, wp2);
      if (a == 0){
        #pragma unroll
        for(int j=0;j<16;j++) wsm2[j] = pack2f(nq_wsm[o*32+2*j], nq_wsm[o*32+2*j+1]);
      }
      for(int t=0; t<T; t+=2){
        float r0, r1;
        equi_mv_val2(SX2 + t*352, SX2 + (t+1)*352, a, pr, wd2, wp2, wsm2, r0, r1);
        SH[t*864 + a*48 + o] = r0;
        SH[(t+1)*864 + a*48 + o] = r1;
      }
    } else {
      int o = out - 768;  // 0..95
      u64 wss2[16], wms2[8];
      #pragma unroll
      for(int j=0;j<16;j++) wss2[j] = pack2f(nq_wss[o*32+2*j], nq_wss[o*32+2*j+1]);
      #pragma unroll
      for(int i=0;i<8;i++)  wms2[i] = pack2f(nq_wms[o*16+2*i], nq_wms[o*16+2*i+1]);
      for(int t=0; t<T; t+=2){
        float r0, r1;
        equi_s_val2(SX2 + t*352, SX2 + (t+1)*352, wss2, wms2, r0, r1);
        SH[t*864 + 768 + o] = r0;
        SH[(t+1)*864 + 768 + o] = r1;
      }
    }
  }
  __syncthreads();

  // ---- stage 10: pack Q/K/V ----
  for(int idx=tid; idx<8*T*20; idx+=NT){           // Q
    int h = idx/(T*20), rem = idx%(T*20), t = rem/20, e = rem%20;
    float v;
    if (e < 16){ int ci=e>>3, ib=e&7, a=c_iblades[ib]; v = SH[t*864 + a*48 + (h*2+ci)]; }
    else       { v = SH[t*864 + 768 + h*4 + (e-16)]; }
    g_Q[((size_t)(b*8+h)*NSEQ + n0 + t)*20 + e] = v;
  }
  for(int idx=tid; idx<8*T*20; idx+=NT){           // K
    int h = idx/(T*20), rem = idx%(T*20), t = rem/20, e = rem%20;
    float v;
    if (e < 16){ int ci=e>>3, ib=e&7, a=c_iblades[ib]; v = SH[t*864 + a*48 + (16 + h*2+ci)]; }
    else       { v = SH[t*864 + 768 + 32 + h*4 + (e-16)]; }
    g_K[((size_t)(b*8+h)*NSEQ + n0 + t)*20 + e] = v;
  }
  for(int idx=tid; idx<8*T*36; idx+=NT){           // V
    int h = idx/(T*36), rem = idx%(T*36), t = rem/36, e = rem%36;
    float v;
    if (e < 32){ int ci=e>>4, a=e&15; v = SH[t*864 + a*48 + (32 + h*2+ci)]; }
    else       { v = SH[t*864 + 768 + 64 + h*4 + (e-32)]; }
    g_V[((size_t)(b*8+h)*NSEQ + n0 + t)*36 + e] = v;
  }
}

// ---------------- final projection + mean ----------------
__global__ void final_kernel(const float* __restrict__ wout_mv,
                             const float* __restrict__ wout_sm,
                             float* __restrict__ out){
  int b = blockIdx.x, tid = threadIdx.x;
  __shared__ float red[256];
  float acc = 0.f;
  for(int n=tid; n<NSEQ; n+=256){
    size_t t = (size_t)b*NSEQ + n;
    const float* M = g_mv + t*256;
    const float* S = g_s + t*32;
    float v = 0.f;
    #pragma unroll
    for(int i=0;i<16;i++) v += wout_mv[i*9] * M[i*16];
    #pragma unroll
    for(int j=0;j<32;j++) v += wout_sm[j] * S[j];
    acc += v;
  }
  red[tid] = acc; __syncthreads();
  for(int s=128; s; s>>=1){ if (tid < s) red[tid] += red[tid+s]; __syncthreads(); }
  if (tid == 0) out[b] = red[0] * (1.f/NSEQ);
}

// ---------------- host ----------------
extern "C" void kernel_launch(void* const* d_in, const int* in_sizes, int n_in,
                              void* d_out, int out_size) {
  const float* inputs    = (const float*)d_in[0];
  const float* win_mv    = (const float*)d_in[1];
  const float* win_bs    = (const float*)d_in[3];
  const float* qkv_wmv   = (const float*)d_in[4];
  const float* qkv_wsm   = (const float*)d_in[5];
  const float* qkv_wms   = (const float*)d_in[6];
  const float* qkv_wss   = (const float*)d_in[7];
  const float* aout_wmv  = (const float*)d_in[8];
  const float* aout_wsm  = (const float*)d_in[9];
  const float* aout_wms  = (const float*)d_in[10];
  const float* aout_wss  = (const float*)d_in[11];
  const float* m1_wmv    = (const float*)d_in[12];
  const float* m1_wsm    = (const float*)d_in[13];
  const float* m1_wms    = (const float*)d_in[14];
  const float* m1_wss    = (const float*)d_in[15];
  const float* m2_wmv    = (const float*)d_in[16];
  const float* m2_wsm    = (const float*)d_in[17];
  const float* m2_wms    = (const float*)d_in[18];
  const float* m2_wss    = (const float*)d_in[19];
  const float* wout_mv   = (const float*)d_in[20];
  const float* wout_sm   = (const float*)d_in[21];

  const int smem_qkv  = (16*352 + 16*864) * 4;                        // 77824
  const int smem_blk  = (16*352 + 16*304 + 16*8*NSPLIT + 16*864) * 4; // 99328
  const int smem_attn = (2*640 + 2*1152) * 16;                        // 57344
  cudaFuncSetAttribute((const void*)qkv_kernel,
                       cudaFuncAttributeMaxDynamicSharedMemorySize, smem_qkv);
  cudaFuncSetAttribute((const void*)block2_kernel<true>,
                       cudaFuncAttributeMaxDynamicSharedMemorySize, smem_blk);
  cudaFuncSetAttribute((const void*)block2_kernel<false>,
                       cudaFuncAttributeMaxDynamicSharedMemorySize, smem_blk);
  cudaFuncSetAttribute((const void*)block2_kernel<true>,
                       cudaFuncAttributePreferredSharedMemoryCarveout, 100);
  cudaFuncSetAttribute((const void*)block2_kernel<false>,
                       cudaFuncAttributePreferredSharedMemoryCarveout, 100);
  cudaFuncSetAttribute((const void*)attn_kernel,
                       cudaFuncAttributeMaxDynamicSharedMemorySize, smem_attn);

  embed_kernel<<<(NTOK*48 + 255)/256, 256>>>(inputs, win_mv, win_bs);

  qkv_kernel<<<NTOK/16, 864, smem_qkv>>>(
      qkv_wmv, qkv_wsm, qkv_wms, qkv_wss);

  for (int l = 0; l < 8; l++){
    attn_kernel<<<dim3(64, NSEQ/256, NSPLIT), 128, smem_attn>>>();
    if (l < 7){
      int ln = l + 1;
      block2_kernel<true><<<NTOK/16, 320, smem_blk>>>(
          aout_wmv + (size_t)l*16*16*9, aout_wsm + (size_t)l*16*32,
          aout_wms + (size_t)l*32*16,   aout_wss + (size_t)l*32*32,
          m1_wmv  + (size_t)l*32*16*9,  m1_wsm  + (size_t)l*32*32,
          m1_wms  + (size_t)l*64*16,    m1_wss  + (size_t)l*64*32,
          m2_wmv  + (size_t)l*16*16*9,  m2_wsm  + (size_t)l*16*32,
          m2_wms  + (size_t)l*32*16,    m2_wss  + (size_t)l*32*32,
          qkv_wmv + (size_t)ln*48*16*9, qkv_wsm + (size_t)ln*48*32,
          qkv_wms + (size_t)ln*96*16,   qkv_wss + (size_t)ln*96*32);
    } else {
      block2_kernel<false><<<NTOK/16, 320, smem_blk>>>(
          aout_wmv + (size_t)l*16*16*9, aout_wsm + (size_t)l*16*32,
          aout_wms + (size_t)l*32*16,   aout_wss + (size_t)l*32*32,
          m1_wmv  + (size_t)l*32*16*9,  m1_wsm  + (size_t)l*32*32,
          m1_wms  + (size_t)l*64*16,    m1_wss  + (size_t)l*64*32,
          m2_wmv  + (size_t)l*16*16*9,  m2_wsm  + (size_t)l*16*32,
          m2_wms  + (size_t)l*32*16,    m2_wss  + (size_t)l*32*32,
          qkv_wmv, qkv_wsm, qkv_wms, qkv_wss);
    }
  }

  final_kernel<<<NBAT, 256>>>(wout_mv, wout_sm, (float*)d_out);
}

// round 16
// speedup vs baseline: 1.3150x; 1.1549x over previous
#include <cuda_runtime.h>
#include <math.h>

#define NTOK 8192
#define NSEQ 1024
#define NBAT 8
#define NSPLIT 4

typedef unsigned long long u64;

// ---------------- f32x2 packed helpers (Blackwell) ----------------
__device__ __forceinline__ u64 pack2f(float lo, float hi){
  u64 r; asm("mov.b64 %0, {%1, %2};" : "=l"(r) : "f"(lo), "f"(hi)); return r;
}
__device__ __forceinline__ u64 ffma2(u64 a, u64 b, u64 c){
  u64 d; asm("fma.rn.f32x2 %0, %1, %2, %3;" : "=l"(d) : "l"(a), "l"(b), "l"(c)); return d;
}
__device__ __forceinline__ u64 fmul2(u64 a, u64 b){
  u64 d; asm("mul.rn.f32x2 %0, %1, %2;" : "=l"(d) : "l"(a), "l"(b)); return d;
}
__device__ __forceinline__ u64 fadd2(u64 a, u64 b){
  u64 d; asm("add.rn.f32x2 %0, %1, %2;" : "=l"(d) : "l"(a), "l"(b)); return d;
}
__device__ __forceinline__ float hadd2(u64 v){
  float a,b; asm("mov.b64 {%0, %1}, %2;" : "=f"(a), "=f"(b) : "l"(v)); return a+b;
}
__device__ __forceinline__ u64 lo2(float4 v){ return pack2f(v.x, v.y); }
__device__ __forceinline__ u64 hi2(float4 v){ return pack2f(v.z, v.w); }
// ---------------- cp.async helpers ----------------
__device__ __forceinline__ void cpa16(void* s, const void* g){
  unsigned sa = (unsigned)__cvta_generic_to_shared(s);
  asm volatile("cp.async.cg.shared.global [%0], [%1], 16;" :: "r"(sa), "l"(g));
}
__device__ __forceinline__ void cpa_commit(){ asm volatile("cp.async.commit_group;"); }
__device__ __forceinline__ void cpa_wait0(){ asm volatile("cp.async.wait_group 0;"); }

// ---------------- device scratch ----------------
__device__ float g_mv [NTOK*256];
__device__ float g_s  [NTOK*32];
__device__ float g_Q[(size_t)64*NSEQ*20];
__device__ float g_K[(size_t)64*NSEQ*20];
__device__ float g_V[(size_t)64*NSEQ*36];
__device__ float g_Osp[(size_t)64*NSEQ*NSPLIT*38];   // [bh][n][split][36 acc + m + l]

// ---------------- blade tables ----------------
__constant__ int   c_kdiag[16] = {0,1,1,1,1,2,2,2,2,2,2,3,3,3,3,4};
__constant__ int   c_pair [16] = {-1,0,-1,-1,-1,2,3,4,-1,-1,-1,8,9,10,-1,14};
__constant__ int   c_koff [16] = {0,5,0,0,0,6,6,6,0,0,0,7,7,7,0,8};
__constant__ float c_inner[16] = {1,0,1,1,1,0,0,0,1,1,1,0,0,0,1,0};
__constant__ int   c_iblades[8]= {0,2,3,4,8,9,10,14};

// compile-time blade algebra (geometric product)
__host__ __device__ constexpr int blade_mask(int i){
  return i==0?0: i==1?1: i==2?2: i==3?4: i==4?8: i==5?3: i==6?5: i==7?9:
         i==8?6: i==9?10: i==10?12: i==11?7: i==12?11: i==13?13: i==14?14: 15;
}
__host__ __device__ constexpr int mask_idx(int m){
  return m==0?0: m==1?1: m==2?2: m==3?5: m==4?3: m==5?6: m==6?8: m==7?11:
         m==8?4: m==9?7: m==10?9: m==11?12: m==12?10: m==13?13: m==14?14: 15;
}
__host__ __device__ constexpr int pc4(int v){ return (v&1)+((v>>1)&1)+((v>>2)&1)+((v>>3)&1); }
__host__ __device__ constexpr int gp_par(int ma,int mb){
  return ( ((mb&1)?pc4(ma>>1):0) + (((mb>>1)&1)?pc4(ma>>2):0) + (((mb>>2)&1)?pc4(ma>>3):0) ) & 1;
}
template<int I,int J>
__device__ __forceinline__ void gp_term(float (&acc)[16], const float* x, const float* y){
  constexpr int ma = blade_mask(I);
  constexpr int mb = blade_mask(J);
  if constexpr (!(ma & mb & 1)) {
    constexpr int k  = mask_idx(ma ^ mb);
    constexpr int sg = gp_par(ma, mb);
    float p = x[I]*y[J];
    if constexpr (sg) acc[k] -= p; else acc[k] += p;
  }
}
#define GP_ROW(I) \
  gp_term<I,0>(acc,x,y);  gp_term<I,1>(acc,x,y);  gp_term<I,2>(acc,x,y);  gp_term<I,3>(acc,x,y); \
  gp_term<I,4>(acc,x,y);  gp_term<I,5>(acc,x,y);  gp_term<I,6>(acc,x,y);  gp_term<I,7>(acc,x,y); \
  gp_term<I,8>(acc,x,y);  gp_term<I,9>(acc,x,y);  gp_term<I,10>(acc,x,y); gp_term<I,11>(acc,x,y);\
  gp_term<I,12>(acc,x,y); gp_term<I,13>(acc,x,y); gp_term<I,14>(acc,x,y); gp_term<I,15>(acc,x,y);

__device__ __forceinline__ float gelu_f(float v){
  float v3 = v*v*v;
  return 0.5f*v*(1.f + tanhf(0.7978845608028654f*(v + 0.044715f*v3)));
}

// ---- equi building blocks: TWO tokens per call, float4 (LDS.128) loads ----
__device__ __forceinline__ void load_wmv_row(const float* wmv, int o, int kd, int ko, int pr,
                                             u64* wd2, u64* wp2){
  #pragma unroll
  for(int i=0;i<8;i++)
    wd2[i] = pack2f(wmv[o*144 + (2*i)*9 + kd], wmv[o*144 + (2*i+1)*9 + kd]);
  if (pr >= 0){
    #pragma unroll
    for(int i=0;i<8;i++)
      wp2[i] = pack2f(wmv[o*144 + (2*i)*9 + ko], wmv[o*144 + (2*i+1)*9 + ko]);
  }
}
__device__ __forceinline__ void equi_mv_val2(const float* X0, const float* X1, int a, int pr,
    const u64* wd2, const u64* wp2, const u64* wsm2, float& r0, float& r1){
  const float4* A0 = (const float4*)(X0 + a*20);
  const float4* A1 = (const float4*)(X1 + a*20);
  u64 p0, p1, q0, q1;
  {
    float4 f0 = A0[0], f1 = A0[1], g0 = A1[0], g1 = A1[1];
    p0 = fmul2(wd2[0], lo2(f0)); p1 = fmul2(wd2[1], hi2(f0));
    q0 = fmul2(wd2[0], lo2(g0)); q1 = fmul2(wd2[1], hi2(g0));
    p0 = ffma2(wd2[2], lo2(f1), p0); p1 = ffma2(wd2[3], hi2(f1), p1);
    q0 = ffma2(wd2[2], lo2(g1), q0); q1 = ffma2(wd2[3], hi2(g1), q1);
    float4 f2 = A0[2], f3 = A0[3], g2 = A1[2], g3 = A1[3];
    p0 = ffma2(wd2[4], lo2(f2), p0); p1 = ffma2(wd2[5], hi2(f2), p1);
    q0 = ffma2(wd2[4], lo2(g2), q0); q1 = ffma2(wd2[5], hi2(g2), q1);
    p0 = ffma2(wd2[6], lo2(f3), p0); p1 = ffma2(wd2[7], hi2(f3), p1);
    q0 = ffma2(wd2[6], lo2(g3), q0); q1 = ffma2(wd2[7], hi2(g3), q1);
  }
  if (pr >= 0){
    const float4* B0 = (const float4*)(X0 + pr*20);
    const float4* B1 = (const float4*)(X1 + pr*20);
    float4 f0 = B0[0], f1 = B0[1], g0 = B1[0], g1 = B1[1];
    p0 = ffma2(wp2[0], lo2(f0), p0); p1 = ffma2(wp2[1], hi2(f0), p1);
    q0 = ffma2(wp2[0], lo2(g0), q0); q1 = ffma2(wp2[1], hi2(g0), q1);
    p0 = ffma2(wp2[2], lo2(f1), p0); p1 = ffma2(wp2[3], hi2(f1), p1);
    q0 = ffma2(wp2[2], lo2(g1), q0); q1 = ffma2(wp2[3], hi2(g1), q1);
    float4 f2 = B0[2], f3 = B0[3], g2 = B1[2], g3 = B1[3];
    p0 = ffma2(wp2[4], lo2(f2), p0); p1 = ffma2(wp2[5], hi2(f2), p1);
    q0 = ffma2(wp2[4], lo2(g2), q0); q1 = ffma2(wp2[5], hi2(g2), q1);
    p0 = ffma2(wp2[6], lo2(f3), p0); p1 = ffma2(wp2[7], hi2(f3), p1);
    q0 = ffma2(wp2[6], lo2(g3), q0); q1 = ffma2(wp2[7], hi2(g3), q1);
  }
  if (a == 0){
    const float4* S0 = (const float4*)(X0 + 320);
    const float4* S1 = (const float4*)(X1 + 320);
    #pragma unroll
    for(int c=0;c<8;c++){
      float4 f = S0[c], g = S1[c];
      p0 = ffma2(wsm2[2*c], lo2(f), p0); p1 = ffma2(wsm2[2*c+1], hi2(f), p1);
      q0 = ffma2(wsm2[2*c], lo2(g), q0); q1 = ffma2(wsm2[2*c+1], hi2(g), q1);
    }
  }
  r0 = hadd2(fadd2(p0, p1));
  r1 = hadd2(fadd2(q0, q1));
}
__device__ __forceinline__ void equi_s_val2(const float* X0, const float* X1,
    const u64* wss2, const u64* wms2, float& r0, float& r1){
  const float4* S0 = (const float4*)(X0 + 320);
  const float4* S1 = (const float4*)(X1 + 320);
  u64 p0, p1, q0, q1;
  {
    float4 f = S0[0], g = S1[0];
    p0 = fmul2(wss2[0], lo2(f)); p1 = fmul2(wss2[1], hi2(f));
    q0 = fmul2(wss2[0], lo2(g)); q1 = fmul2(wss2[1], hi2(g));
  }
  #pragma unroll
  for(int c=1;c<8;c++){
    float4 f = S0[c], g = S1[c];
    p0 = ffma2(wss2[2*c], lo2(f), p0); p1 = ffma2(wss2[2*c+1], hi2(f), p1);
    q0 = ffma2(wss2[2*c], lo2(g), q0); q1 = ffma2(wss2[2*c+1], hi2(g), q1);
  }
  const float4* Z0 = (const float4*)(X0);
  const float4* Z1 = (const float4*)(X1);
  #pragma unroll
  for(int c=0;c<4;c++){
    float4 f = Z0[c], g = Z1[c];
    p0 = ffma2(wms2[2*c], lo2(f), p0); p1 = ffma2(wms2[2*c+1], hi2(f), p1);
    q0 = ffma2(wms2[2*c], lo2(g), q0); q1 = ffma2(wms2[2*c+1], hi2(g), q1);
  }
  r0 = hadd2(fadd2(p0, p1));
  r1 = hadd2(fadd2(q0, q1));
}

// ---------------- embed ----------------
__global__ void embed_kernel(const float* __restrict__ inp,
                             const float* __restrict__ win_mv,
                             const float* __restrict__ win_bs){
  int idx = blockIdx.x*blockDim.x + threadIdx.x;
  if (idx < NTOK*16){
    int t = idx>>4, o = idx&15;
    float x = inp[t*3+0], y = inp[t*3+1], z = inp[t*3+2];
    float w3 = win_mv[o*9+3], w8 = win_mv[o*9+8];
    float* M = g_mv + (size_t)t*256 + o*16;
    #pragma unroll
    for(int a=0;a<16;a++) M[a]=0.f;
    M[11] = -z*w3;  M[12] = y*w3;  M[13] = -x*w3;  M[14] = w3;  M[15] = w8;
  } else if (idx < NTOK*16 + NTOK*32){
    int r = idx - NTOK*16; int t = r>>5, j = r&31;
    g_s[t*32+j] = win_bs[j];
  }
}

// ---------------- LN + QKV equi, staged coalesced pack (layer 0 only) ------
__global__ void __launch_bounds__(864) qkv_kernel(
    const float* __restrict__ wmv, const float* __restrict__ wsm,
    const float* __restrict__ wms, const float* __restrict__ wss)
{
  constexpr int T = 16, NT = 864;
  extern __shared__ float sm[];
  float* SX = sm;            // T*352
  float* SY = sm + T*352;    // T*864
  const int tid = threadIdx.x;
  const size_t t0 = (size_t)blockIdx.x * T;
  const int b = (int)(t0 >> 10), n0 = (int)(t0 & 1023);

  for(int idx=tid; idx<T*256; idx+=NT){
    int t = idx>>8, r = idx&255, i = r>>4, a = r&15;
    SX[t*352 + a*20 + i] = g_mv[(t0+t)*256 + r];
  }
  for(int idx=tid; idx<T*32; idx+=NT){
    int t = idx>>5, j = idx&31;
    SX[t*352 + 320 + j] = g_s[(t0+t)*32 + j];
  }
  __syncthreads();

  { // LN: warp w -> token w
    int w = tid>>5, lane = tid&31;
    if (w < T){
      float* X = SX + w*352;
      int a = lane>>1;
      int base = a*20 + (lane&1)*8;
      float msk = c_inner[a];
      float ss = 0.f;
      #pragma unroll
      for(int r=0;r<8;r++){ float v = X[base+r]; ss += v*v*msk; }
      #pragma unroll
      for(int off=16;off;off>>=1) ss += __shfl_xor_sync(0xffffffffu, ss, off);
      float sc = rsqrtf(ss*0.0625f + 1e-6f);
      #pragma unroll
      for(int r=0;r<8;r++) X[base+r] *= sc;
      float v = X[320+lane];
      float s2 = v*v;
      #pragma unroll
      for(int off=16;off;off>>=1) s2 += __shfl_xor_sync(0xffffffffu, s2, off);
      X[320+lane] = v * rsqrtf(s2*0.03125f + 1e-6f);
    }
  }
  __syncthreads();

  if (tid < 768){
    int o = tid % 48, a = tid / 48;
    int kd = c_kdiag[a], pr = c_pair[a], ko = c_koff[a];
    u64 wd2[8], wp2[8], wsm2[16];
    load_wmv_row(wmv, o, kd, ko, pr, wd2, wp2);
    if (a == 0){
      #pragma unroll
      for(int j=0;j<16;j++) wsm2[j] = pack2f(wsm[o*32+2*j], wsm[o*32+2*j+1]);
    }
    for(int t=0; t<T; t+=2){
      float r0, r1;
      equi_mv_val2(SX + t*352, SX + (t+1)*352, a, pr, wd2, wp2, wsm2, r0, r1);
      SY[t*864 + a*48 + o] = r0;
      SY[(t+1)*864 + a*48 + o] = r1;
    }
  } else {
    int o = tid - 768;  // 0..95
    u64 wss2[16], wms2[8];
    #pragma unroll
    for(int j=0;j<16;j++) wss2[j] = pack2f(wss[o*32+2*j], wss[o*32+2*j+1]);
    #pragma unroll
    for(int i=0;i<8;i++)  wms2[i] = pack2f(wms[o*16+2*i], wms[o*16+2*i+1]);
    for(int t=0; t<T; t+=2){
      float r0, r1;
      equi_s_val2(SX + t*352, SX + (t+1)*352, wss2, wms2, r0, r1);
      SY[t*864 + 768 + o] = r0;
      SY[(t+1)*864 + 768 + o] = r1;
    }
  }
  __syncthreads();

  for(int idx=tid; idx<8*T*20; idx+=NT){           // Q
    int h = idx/(T*20), rem = idx%(T*20), t = rem/20, e = rem%20;
    float v;
    if (e < 16){ int ci=e>>3, ib=e&7, a=c_iblades[ib]; v = SY[t*864 + a*48 + (h*2+ci)]; }
    else       { v = SY[t*864 + 768 + h*4 + (e-16)]; }
    g_Q[((size_t)(b*8+h)*NSEQ + n0 + t)*20 + e] = v;
  }
  for(int idx=tid; idx<8*T*20; idx+=NT){           // K
    int h = idx/(T*20), rem = idx%(T*20), t = rem/20, e = rem%20;
    float v;
    if (e < 16){ int ci=e>>3, ib=e&7, a=c_iblades[ib]; v = SY[t*864 + a*48 + (16 + h*2+ci)]; }
    else       { v = SY[t*864 + 768 + 32 + h*4 + (e-16)]; }
    g_K[((size_t)(b*8+h)*NSEQ + n0 + t)*20 + e] = v;
  }
  for(int idx=tid; idx<8*T*36; idx+=NT){           // V
    int h = idx/(T*36), rem = idx%(T*36), t = rem/36, e = rem%36;
    float v;
    if (e < 32){ int ci=e>>4, a=e&15; v = SY[t*864 + a*48 + (32 + h*2+ci)]; }
    else       { v = SY[t*864 + 768 + 64 + h*4 + (e-32)]; }
    g_V[((size_t)(b*8+h)*NSEQ + n0 + t)*36 + e] = v;
  }
}

// ---------------- attention: plain-sum softmax (exp2 domain), 2 q/thread ----
__global__ void __launch_bounds__(128) attn_kernel(){
  const int bh = blockIdx.x, qt = blockIdx.y, z = blockIdx.z, tid = threadIdx.x;
  const int qi0 = qt*256 + tid;
  // 1/sqrt(20) * log2(e): scores land directly in exp2 domain
  const float SCALE = 0.22360679774997896f * 1.4426950408889634f;

  extern __shared__ float4 dyn4[];
  float4* sk4 = dyn4;            // 2 x 640
  float4* sv4 = dyn4 + 1280;     // 2 x 1152

  u64 q0[10], q1[10];
  {
    const float* qp0 = g_Q + ((size_t)bh*NSEQ + qi0)*20;
    const float* qp1 = qp0 + 128*20;
    #pragma unroll
    for(int c=0;c<10;c++){
      q0[c] = pack2f(qp0[2*c]*SCALE, qp0[2*c+1]*SCALE);
      q1[c] = pack2f(qp1[2*c]*SCALE, qp1[2*c+1]*SCALE);
    }
  }
  float l0=0.f, l1=0.f;
  u64 a0[18], a1[18];
  #pragma unroll
  for(int c=0;c<18;c++){ a0[c]=0ull; a1[c]=0ull; }

  const int kt0 = z*2;
  const float4* kp = (const float4*)(g_K + (size_t)bh*NSEQ*20) + kt0*128*5;
  const float4* vp = (const float4*)(g_V + (size_t)bh*NSEQ*36) + kt0*128*9;

  #pragma unroll
  for(int i=0;i<5;i++) cpa16(&sk4[tid + 128*i], &kp[tid + 128*i]);
  #pragma unroll
  for(int i=0;i<9;i++) cpa16(&sv4[tid + 128*i], &vp[tid + 128*i]);
  cpa_commit();
  cpa_wait0();
  __syncthreads();

  for(int ki=0; ki<2; ki++){
    const int cur = ki & 1, nxt = cur ^ 1;
    if (ki < 1){
      const float4* kpn = kp + 128*5;
      const float4* vpn = vp + 128*9;
      #pragma unroll
      for(int i=0;i<5;i++) cpa16(&sk4[nxt*640 + tid + 128*i], &kpn[tid + 128*i]);
      #pragma unroll
      for(int i=0;i<9;i++) cpa16(&sv4[nxt*1152 + tid + 128*i], &vpn[tid + 128*i]);
      cpa_commit();
    }
    const float4* skc = sk4 + cur*640;
    const float4* svc = sv4 + cur*1152;

    #pragma unroll 2
    for(int j=0; j<128; j++){
      const float4* kk4 = skc + j*5;
      float4 k0 = kk4[0], k1 = kk4[1], k2 = kk4[2], k3 = kk4[3], k4 = kk4[4];
      u64 t0a = fmul2(q0[0], lo2(k0)), t0b = fmul2(q0[1], hi2(k0));
      u64 t1a = fmul2(q1[0], lo2(k0)), t1b = fmul2(q1[1], hi2(k0));
      t0a = ffma2(q0[2], lo2(k1), t0a); t0b = ffma2(q0[3], hi2(k1), t0b);
      t1a = ffma2(q1[2], lo2(k1), t1a); t1b = ffma2(q1[3], hi2(k1), t1b);
      t0a = ffma2(q0[4], lo2(k2), t0a); t0b = ffma2(q0[5], hi2(k2), t0b);
      t1a = ffma2(q1[4], lo2(k2), t1a); t1b = ffma2(q1[5], hi2(k2), t1b);
      t0a = ffma2(q0[6], lo2(k3), t0a); t0b = ffma2(q0[7], hi2(k3), t0b);
      t1a = ffma2(q1[6], lo2(k3), t1a); t1b = ffma2(q1[7], hi2(k3), t1b);
      t0a = ffma2(q0[8], lo2(k4), t0a); t0b = ffma2(q0[9], hi2(k4), t0b);
      t1a = ffma2(q1[8], lo2(k4), t1a); t1b = ffma2(q1[9], hi2(k4), t1b);
      float p0 = exp2f(hadd2(fadd2(t0a, t0b)));
      float p1 = exp2f(hadd2(fadd2(t1a, t1b)));
      l0 += p0; l1 += p1;
      u64 pp0 = pack2f(p0, p0), pp1 = pack2f(p1, p1);
      const float4* vv4 = svc + j*9;
      #pragma unroll
      for(int i=0;i<9;i++){
        float4 v4 = vv4[i];
        u64 vl = lo2(v4), vh = hi2(v4);
        a0[2*i]   = ffma2(pp0, vl, a0[2*i]);
        a0[2*i+1] = ffma2(pp0, vh, a0[2*i+1]);
        a1[2*i]   = ffma2(pp1, vl, a1[2*i]);
        a1[2*i+1] = ffma2(pp1, vh, a1[2*i+1]);
      }
    }
    if (ki < 1){
      cpa_wait0();
      __syncthreads();
    }
  }
  float* op0 = g_Osp + ((size_t)(bh*NSEQ + qi0)*NSPLIT + z)*38;
  float* op1 = g_Osp + ((size_t)(bh*NSEQ + qi0 + 128)*NSPLIT + z)*38;
  #pragma unroll
  for(int c=0;c<18;c++){
    ((u64*)op0)[c] = a0[c];
    ((u64*)op1)[c] = a1[c];
  }
  op0[36] = 0.f; op0[37] = l0;
  op1[36] = 0.f; op1[37] = l1;
}

// ---- fused: merge + out-proj + res + LN + mlp1 + GP + mlp2 + res (+ next QKV)
// NT=320 with 2 resident blocks/SM (regs 2*320*96 < 64K, smem 2*97KB < 228KB)
template<bool FQ>
__global__ void __launch_bounds__(320, 2) block2_kernel(
    const float* __restrict__ ao_wmv, const float* __restrict__ ao_wsm,
    const float* __restrict__ ao_wms, const float* __restrict__ ao_wss,
    const float* __restrict__ m1_wmv, const float* __restrict__ m1_wsm,
    const float* __restrict__ m1_wms, const float* __restrict__ m1_wss,
    const float* __restrict__ m2_wmv, const float* __restrict__ m2_wsm,
    const float* __restrict__ m2_wms, const float* __restrict__ m2_wss,
    const float* __restrict__ nq_wmv, const float* __restrict__ nq_wsm,
    const float* __restrict__ nq_wms, const float* __restrict__ nq_wss)
{
  constexpr int T = 16, NT = 320, SRS = 304;
  extern __shared__ float sm[];
  float* SA  = sm;                 // T*352  attn-out (blade-major); later SX2
  float* SR  = SA + T*352;         // T*304  residual [o*17+a], scalars at 272
  float* SW  = SR + T*SRS;         // T*8*NSPLIT merge weights
  float* SH  = SW + T*8*NSPLIT;    // T*864 region: mlp1 hidden (608) / qkv SY (864)
  float* SX2 = SA;
  const int tid = threadIdx.x;
  const size_t t0 = (size_t)blockIdx.x * T;
  const int b = (int)(t0 >> 10), n0 = (int)(t0 & 1023);

  // ---- stage 0: merge weights + residual loads ----
  if (tid < T*8){
    int t = tid>>3, h = tid&7;
    const float* p = g_Osp + (((size_t)(b*8+h)*NSEQ + n0 + t)*NSPLIT)*38;
    float m[NSPLIT], l[NSPLIT];
    float mm = -1e30f;
    #pragma unroll
    for(int z=0;z<NSPLIT;z++){ m[z]=p[z*38+36]; l[z]=p[z*38+37]; mm = fmaxf(mm, m[z]); }
    float den = 0.f, w[NSPLIT];
    #pragma unroll
    for(int z=0;z<NSPLIT;z++){ w[z] = __expf(m[z]-mm); den += l[z]*w[z]; }
    float inv = 1.f/den;
    #pragma unroll
    for(int z=0;z<NSPLIT;z++) SW[tid*NSPLIT + z] = w[z]*inv;
  }
  for(int idx=tid; idx<T*256; idx+=NT){
    int t = idx>>8, r = idx&255;
    SR[t*SRS + (r>>4)*17 + (r&15)] = g_mv[(t0+t)*256 + r];
  }
  for(int idx=tid; idx<T*32; idx+=NT){
    int t = idx>>5, j = idx&31;
    SR[t*SRS + 272 + j] = g_s[(t0+t)*32 + j];
  }
  __syncthreads();

  // ---- stage 1: merged attn-out -> SA (blade-major) ----
  for(int idx=tid; idx<T*288; idx+=NT){
    int t = idx/288, r = idx%288;
    int h = r/36, e = r%36;
    const float* p = g_Osp + (((size_t)(b*8+h)*NSEQ + n0 + t)*NSPLIT)*38;
    const float* wv = SW + (t*8+h)*NSPLIT;
    float v = 0.f;
    #pragma unroll
    for(int z=0;z<NSPLIT;z++) v += p[z*38 + e] * wv[z];
    if (e < 32){ int ci=e>>4, a=e&15; SA[t*352 + a*20 + (h*2+ci)] = v; }
    else       { SA[t*352 + 320 + h*4 + (e-32)] = v; }
  }
  __syncthreads();

  // ---- stage 2: out-projection equi + residual add into SR ----
  if (tid < 288){
    int out = tid;
    if (out < 256){
      int o = out & 15, a = out >> 4;
      int kd = c_kdiag[a], pr = c_pair[a], ko = c_koff[a];
      u64 wd2[8], wp2[8], wsm2[16];
      load_wmv_row(ao_wmv, o, kd, ko, pr, wd2, wp2);
      if (a == 0){
        #pragma unroll
        for(int j=0;j<16;j++) wsm2[j] = pack2f(ao_wsm[o*32+2*j], ao_wsm[o*32+2*j+1]);
      }
      #pragma unroll
      for(int t=0; t<T; t+=2){
        float r0, r1;
        equi_mv_val2(SA + t*352, SA + (t+1)*352, a, pr, wd2, wp2, wsm2, r0, r1);
        SR[t*SRS + o*17 + a] += r0;
        SR[(t+1)*SRS + o*17 + a] += r1;
      }
    } else {
      int o = out - 256;
      u64 wss2[16], wms2[8];
      #pragma unroll
      for(int j=0;j<16;j++) wss2[j] = pack2f(ao_wss[o*32+2*j], ao_wss[o*32+2*j+1]);
      #pragma unroll
      for(int i=0;i<8;i++)  wms2[i] = pack2f(ao_wms[o*16+2*i], ao_wms[o*16+2*i+1]);
      #pragma unroll
      for(int t=0; t<T; t+=2){
        float r0, r1;
        equi_s_val2(SA + t*352, SA + (t+1)*352, wss2, wms2, r0, r1);
        SR[t*SRS + 272 + o] += r0;
        SR[(t+1)*SRS + 272 + o] += r1;
      }
    }
  }
  __syncthreads();

  // ---- stage 3: LN(SR) -> SX2 ----
  for(int w = tid>>5; w < T; w += NT/32){
    int lane = tid&31;
    const float* R = SR + w*SRS;
    float ss = 0.f;
    #pragma unroll
    for(int r=0;r<8;r++){
      int li = lane + 32*r; int o = li>>4, a = li&15;
      float v = R[o*17 + a]; ss += v*v*c_inner[a];
    }
    #pragma unroll
    for(int off=16;off;off>>=1) ss += __shfl_xor_sync(0xffffffffu, ss, off);
    float sc = rsqrtf(ss*0.0625f + 1e-6f);
    #pragma unroll
    for(int r=0;r<8;r++){
      int li = lane + 32*r; int o = li>>4, a = li&15;
      SX2[w*352 + a*20 + o] = R[o*17 + a]*sc;
    }
    float v = R[272+lane];
    float s2 = v*v;
    #pragma unroll
    for(int off=16;off;off>>=1) s2 += __shfl_xor_sync(0xffffffffu, s2, off);
    SX2[w*352 + 320 + lane] = v * rsqrtf(s2*0.03125f + 1e-6f);
  }
  __syncthreads();

  // ---- stage 4: mlp1 equi (512 mv + 64 s outs over 2 passes) -> SH ----
  #pragma unroll
  for(int pass=0; pass<2; pass++){
    int out = tid + pass*NT;
    if (out < 512){
      int o = out % 32, a = out / 32;
      int kd = c_kdiag[a], pr = c_pair[a], ko = c_koff[a];
      u64 wd2[8], wp2[8], wsm2[16];
      load_wmv_row(m1_wmv, o, kd, ko, pr, wd2, wp2);
      if (a == 0){
        #pragma unroll
        for(int j=0;j<16;j++) wsm2[j] = pack2f(m1_wsm[o*32+2*j], m1_wsm[o*32+2*j+1]);
      }
      #pragma unroll
      for(int t=0; t<T; t+=2){
        float r0, r1;
        equi_mv_val2(SX2 + t*352, SX2 + (t+1)*352, a, pr, wd2, wp2, wsm2, r0, r1);
        SH[t*608 + o*17 + a] = r0;
        SH[(t+1)*608 + o*17 + a] = r1;
      }
    } else if (out < 576){
      int o = out - 512;  // 0..63
      u64 wss2[16], wms2[8];
      #pragma unroll
      for(int j=0;j<16;j++) wss2[j] = pack2f(m1_wss[o*32+2*j], m1_wss[o*32+2*j+1]);
      #pragma unroll
      for(int i=0;i<8;i++)  wms2[i] = pack2f(m1_wms[o*16+2*i], m1_wms[o*16+2*i+1]);
      #pragma unroll
      for(int t=0; t<T; t+=2){
        float r0, r1;
        equi_s_val2(SX2 + t*352, SX2 + (t+1)*352, wss2, wms2, r0, r1);
        SH[t*608 + 544 + o] = r0;
        SH[(t+1)*608 + 544 + o] = r1;
      }
    }
  }
  __syncthreads();

  // ---- stage 5: geometric product + gated gelu -> SX2 ----
  for(int idx=tid; idx<T*48; idx+=NT){
    if (idx < T*16){
      int t = idx>>4, c = idx&15;
      const float* h1 = SH + t*608 + c*17;
      const float* h2 = SH + t*608 + (16+c)*17;
      float x[16], y[16], acc[16];
      #pragma unroll
      for(int i=0;i<16;i++){ x[i]=h1[i]; y[i]=h2[i]; acc[i]=0.f; }
      GP_ROW(0)  GP_ROW(1)  GP_ROW(2)  GP_ROW(3)
      GP_ROW(4)  GP_ROW(5)  GP_ROW(6)  GP_ROW(7)
      GP_ROW(8)  GP_ROW(9)  GP_ROW(10) GP_ROW(11)
      GP_ROW(12) GP_ROW(13) GP_ROW(14) GP_ROW(15)
      float g = gelu_f(acc[0]);
      #pragma unroll
      for(int a=0;a<16;a++) SX2[t*352 + a*20 + c] = acc[a]*g;
    } else {
      int r = idx - T*16; int t = r>>5, j = r&31;
      const float* hs = SH + t*608 + 544;
      SX2[t*352 + 320 + j] = hs[j] * gelu_f(hs[32+j]);
    }
  }
  __syncthreads();

  // ---- stage 6: mlp2 equi + residual add into SR ----
  if (tid < 288){
    int out = tid;
    if (out < 256){
      int o = out & 15, a = out >> 4;
      int kd = c_kdiag[a], pr = c_pair[a], ko = c_koff[a];
      u64 wd2[8], wp2[8], wsm2[16];
      load_wmv_row(m2_wmv, o, kd, ko, pr, wd2, wp2);
      if (a == 0){
        #pragma unroll
        for(int j=0;j<16;j++) wsm2[j] = pack2f(m2_wsm[o*32+2*j], m2_wsm[o*32+2*j+1]);
      }
      #pragma unroll
      for(int t=0; t<T; t+=2){
        float r0, r1;
        equi_mv_val2(SX2 + t*352, SX2 + (t+1)*352, a, pr, wd2, wp2, wsm2, r0, r1);
        SR[t*SRS + o*17 + a] += r0;
        SR[(t+1)*SRS + o*17 + a] += r1;
      }
    } else {
      int o = out - 256;
      u64 wss2[16], wms2[8];
      #pragma unroll
      for(int j=0;j<16;j++) wss2[j] = pack2f(m2_wss[o*32+2*j], m2_wss[o*32+2*j+1]);
      #pragma unroll
      for(int i=0;i<8;i++)  wms2[i] = pack2f(m2_wms[o*16+2*i], m2_wms[o*16+2*i+1]);
      #pragma unroll
      for(int t=0; t<T; t+=2){
        float r0, r1;
        equi_s_val2(SX2 + t*352, SX2 + (t+1)*352, wss2, wms2, r0, r1);
        SR[t*SRS + 272 + o] += r0;
        SR[(t+1)*SRS + 272 + o] += r1;
      }
    }
  }
  __syncthreads();

  // ---- stage 7+8: store residual; if FQ, also LN(SR) -> SX2 ----
  for(int idx=tid; idx<T*256; idx+=NT){
    int t = idx>>8, r = idx&255;
    g_mv[(t0+t)*256 + r] = SR[t*SRS + (r>>4)*17 + (r&15)];
  }
  for(int idx=tid; idx<T*32; idx+=NT){
    int t = idx>>5, j = idx&31;
    g_s[(t0+t)*32 + j] = SR[t*SRS + 272 + j];
  }

  if (!FQ) return;

  for(int w = tid>>5; w < T; w += NT/32){
    int lane = tid&31;
    const float* R = SR + w*SRS;
    float ss = 0.f;
    #pragma unroll
    for(int r=0;r<8;r++){
      int li = lane + 32*r; int o = li>>4, a = li&15;
      float v = R[o*17 + a]; ss += v*v*c_inner[a];
    }
    #pragma unroll
    for(int off=16;off;off>>=1) ss += __shfl_xor_sync(0xffffffffu, ss, off);
    float sc = rsqrtf(ss*0.0625f + 1e-6f);
    #pragma unroll
    for(int r=0;r<8;r++){
      int li = lane + 32*r; int o = li>>4, a = li&15;
      SX2[w*352 + a*20 + o] = R[o*17 + a]*sc;
    }
    float v = R[272+lane];
    float s2 = v*v;
    #pragma unroll
    for(int off=16;off;off>>=1) s2 += __shfl_xor_sync(0xffffffffu, s2, off);
    SX2[w*352 + 320 + lane] = v * rsqrtf(s2*0.03125f + 1e-6f);
  }
  __syncthreads();

  // ---- stage 9: next-layer QKV equi -> SH as SY (stride 864) ----
  for(int out = tid; out < 864; out += NT){
    if (out < 768){
      int o = out % 48, a = out / 48;
      int kd = c_kdiag[a], pr = c_pair[a], ko = c_koff[a];
      u64 wd2[8], wp2[8], wsm2[16];
      load_wmv_row(nq_wmv, o, kd, ko, pr, wd2, wp2);
      if (a == 0){
        #pragma unroll
        for(int j=0;j<16;j++) wsm2[j] = pack2f(nq_wsm[o*32+2*j], nq_wsm[o*32+2*j+1]);
      }
      for(int t=0; t<T; t+=2){
        float r0, r1;
        equi_mv_val2(SX2 + t*352, SX2 + (t+1)*352, a, pr, wd2, wp2, wsm2, r0, r1);
        SH[t*864 + a*48 + o] = r0;
        SH[(t+1)*864 + a*48 + o] = r1;
      }
    } else {
      int o = out - 768;  // 0..95
      u64 wss2[16], wms2[8];
      #pragma unroll
      for(int j=0;j<16;j++) wss2[j] = pack2f(nq_wss[o*32+2*j], nq_wss[o*32+2*j+1]);
      #pragma unroll
      for(int i=0;i<8;i++)  wms2[i] = pack2f(nq_wms[o*16+2*i], nq_wms[o*16+2*i+1]);
      for(int t=0; t<T; t+=2){
        float r0, r1;
        equi_s_val2(SX2 + t*352, SX2 + (t+1)*352, wss2, wms2, r0, r1);
        SH[t*864 + 768 + o] = r0;
        SH[(t+1)*864 + 768 + o] = r1;
      }
    }
  }
  __syncthreads();

  // ---- stage 10: pack Q/K/V ----
  for(int idx=tid; idx<8*T*20; idx+=NT){           // Q
    int h = idx/(T*20), rem = idx%(T*20), t = rem/20, e = rem%20;
    float v;
    if (e < 16){ int ci=e>>3, ib=e&7, a=c_iblades[ib]; v = SH[t*864 + a*48 + (h*2+ci)]; }
    else       { v = SH[t*864 + 768 + h*4 + (e-16)]; }
    g_Q[((size_t)(b*8+h)*NSEQ + n0 + t)*20 + e] = v;
  }
  for(int idx=tid; idx<8*T*20; idx+=NT){           // K
    int h = idx/(T*20), rem = idx%(T*20), t = rem/20, e = rem%20;
    float v;
    if (e < 16){ int ci=e>>3, ib=e&7, a=c_iblades[ib]; v = SH[t*864 + a*48 + (16 + h*2+ci)]; }
    else       { v = SH[t*864 + 768 + 32 + h*4 + (e-16)]; }
    g_K[((size_t)(b*8+h)*NSEQ + n0 + t)*20 + e] = v;
  }
  for(int idx=tid; idx<8*T*36; idx+=NT){           // V
    int h = idx/(T*36), rem = idx%(T*36), t = rem/36, e = rem%36;
    float v;
    if (e < 32){ int ci=e>>4, a=e&15; v = SH[t*864 + a*48 + (32 + h*2+ci)]; }
    else       { v = SH[t*864 + 768 + 64 + h*4 + (e-32)]; }
    g_V[((size_t)(b*8+h)*NSEQ + n0 + t)*36 + e] = v;
  }
}

// ---------------- final projection + mean ----------------
__global__ void final_kernel(const float* __restrict__ wout_mv,
                             const float* __restrict__ wout_sm,
                             float* __restrict__ out){
  int b = blockIdx.x, tid = threadIdx.x;
  __shared__ float red[256];
  float acc = 0.f;
  for(int n=tid; n<NSEQ; n+=256){
    size_t t = (size_t)b*NSEQ + n;
    const float* M = g_mv + t*256;
    const float* S = g_s + t*32;
    float v = 0.f;
    #pragma unroll
    for(int i=0;i<16;i++) v += wout_mv[i*9] * M[i*16];
    #pragma unroll
    for(int j=0;j<32;j++) v += wout_sm[j] * S[j];
    acc += v;
  }
  red[tid] = acc; __syncthreads();
  for(int s=128; s; s>>=1){ if (tid < s) red[tid] += red[tid+s]; __syncthreads(); }
  if (tid == 0) out[b] = red[0] * (1.f/NSEQ);
}

// ---------------- host ----------------
extern "C" void kernel_launch(void* const* d_in, const int* in_sizes, int n_in,
                              void* d_out, int out_size) {
  const float* inputs    = (const float*)d_in[0];
  const float* win_mv    = (const float*)d_in[1];
  const float* win_bs    = (const float*)d_in[3];
  const float* qkv_wmv   = (const float*)d_in[4];
  const float* qkv_wsm   = (const float*)d_in[5];
  const float* qkv_wms   = (const float*)d_in[6];
  const float* qkv_wss   = (const float*)d_in[7];
  const float* aout_wmv  = (const float*)d_in[8];
  const float* aout_wsm  = (const float*)d_in[9];
  const float* aout_wms  = (const float*)d_in[10];
  const float* aout_wss  = (const float*)d_in[11];
  const float* m1_wmv    = (const float*)d_in[12];
  const float* m1_wsm    = (const float*)d_in[13];
  const float* m1_wms    = (const float*)d_in[14];
  const float* m1_wss    = (const float*)d_in[15];
  const float* m2_wmv    = (const float*)d_in[16];
  const float* m2_wsm    = (const float*)d_in[17];
  const float* m2_wms    = (const float*)d_in[18];
  const float* m2_wss    = (const float*)d_in[19];
  const float* wout_mv   = (const float*)d_in[20];
  const float* wout_sm   = (const float*)d_in[21];

  const int smem_qkv  = (16*352 + 16*864) * 4;                        // 77824
  const int smem_blk  = (16*352 + 16*304 + 16*8*NSPLIT + 16*864) * 4; // 99328
  const int smem_attn = (2*640 + 2*1152) * 16;                        // 57344
  cudaFuncSetAttribute((const void*)qkv_kernel,
                       cudaFuncAttributeMaxDynamicSharedMemorySize, smem_qkv);
  cudaFuncSetAttribute((const void*)block2_kernel<true>,
                       cudaFuncAttributeMaxDynamicSharedMemorySize, smem_blk);
  cudaFuncSetAttribute((const void*)block2_kernel<false>,
                       cudaFuncAttributeMaxDynamicSharedMemorySize, smem_blk);
  cudaFuncSetAttribute((const void*)block2_kernel<true>,
                       cudaFuncAttributePreferredSharedMemoryCarveout, 100);
  cudaFuncSetAttribute((const void*)block2_kernel<false>,
                       cudaFuncAttributePreferredSharedMemoryCarveout, 100);
  cudaFuncSetAttribute((const void*)attn_kernel,
                       cudaFuncAttributeMaxDynamicSharedMemorySize, smem_attn);

  embed_kernel<<<(NTOK*48 + 255)/256, 256>>>(inputs, win_mv, win_bs);

  qkv_kernel<<<NTOK/16, 864, smem_qkv>>>(
      qkv_wmv, qkv_wsm, qkv_wms, qkv_wss);

  for (int l = 0; l < 8; l++){
    attn_kernel<<<dim3(64, NSEQ/256, NSPLIT), 128, smem_attn>>>();
    if (l < 7){
      int ln = l + 1;
      block2_kernel<true><<<NTOK/16, 320, smem_blk>>>(
          aout_wmv + (size_t)l*16*16*9, aout_wsm + (size_t)l*16*32,
          aout_wms + (size_t)l*32*16,   aout_wss + (size_t)l*32*32,
          m1_wmv  + (size_t)l*32*16*9,  m1_wsm  + (size_t)l*32*32,
          m1_wms  + (size_t)l*64*16,    m1_wss  + (size_t)l*64*32,
          m2_wmv  + (size_t)l*16*16*9,  m2_wsm  + (size_t)l*16*32,
          m2_wms  + (size_t)l*32*16,    m2_wss  + (size_t)l*32*32,
          qkv_wmv + (size_t)ln*48*16*9, qkv_wsm + (size_t)ln*48*32,
          qkv_wms + (size_t)ln*96*16,   qkv_wss + (size_t)ln*96*32);
    } else {
      block2_kernel<false><<<NTOK/16, 320, smem_blk>>>(
          aout_wmv + (size_t)l*16*16*9, aout_wsm + (size_t)l*16*32,
          aout_wms + (size_t)l*32*16,   aout_wss + (size_t)l*32*32,
          m1_wmv  + (size_t)l*32*16*9,  m1_wsm  + (size_t)l*32*32,
          m1_wms  + (size_t)l*64*16,    m1_wss  + (size_t)l*64*32,
          m2_wmv  + (size_t)l*16*16*9,  m2_wsm  + (size_t)l*16*32,
          m2_wms  + (size_t)l*32*16,    m2_wss  + (size_t)l*32*32,
          qkv_wmv, qkv_wsm, qkv_wms, qkv_wss);
    }
  }

  final_kernel<<<NBAT, 256>>>(wout_mv, wout_sm, (float*)d_out);
}